// round 14
// baseline (speedup 1.0000x reference)
#include <cuda_runtime.h>
#include <math.h>
#include <stdint.h>

#define S_LEN 2048
#define T_LEN 2048
#define BATCH 2
#define EDIM  1024
#define HEADS 16
#define HDIM  64
#define HD    (HEADS*HDIM)   /* 1024 */

// ---------------- scratch (static device globals; no allocation) ----------
__device__ uint32_t g_encH[4096*512], g_encL[4096*512];   // enc  (T*B, E/2)
__device__ uint32_t g_inH [4096*512], g_inL [4096*512];   // inp  (S*B, E/2)
__device__ uint32_t g_WkvH[512*2048], g_WkvL[512*2048];   // Wkv  (E/2, 2HD)
__device__ uint32_t g_WqH [512*1024], g_WqL [512*1024];   // Wq   (E/2, HD)
__device__ uint32_t g_WpH [512*1024], g_WpL [512*1024];   // Wp   (HD/2, E)
__device__ uint32_t g_KhT[BATCH*HEADS*32*T_LEN], g_KlT[BATCH*HEADS*32*T_LEN]; // (B,H,D/2,T)
__device__ uint32_t g_Qh[BATCH*HEADS*S_LEN*32], g_Ql[BATCH*HEADS*S_LEN*32];   // (B,H,S,D/2)
__device__ float    g_V [BATCH*HEADS*T_LEN*HDIM];                              // (B,H,T,D)
__device__ uint32_t g_Vh2[BATCH*HEADS*(T_LEN/2)*HDIM], g_Vl2[BATCH*HEADS*(T_LEN/2)*HDIM]; // (B,H,T/2,D)
__device__ uint32_t g_AVh[4096*512], g_AVl[4096*512];     // (S*B, HD/2)
__device__ int      g_mflag[16*32];                       // per (s-block, j-tile)

// ---------------- bf16 split helpers ---------------------------------------
__device__ __forceinline__ uint32_t bfbits(float x) {
    uint32_t u = __float_as_uint(x);
    return (u + 0x7FFFu + ((u >> 16) & 1u)) & 0xFFFF0000u;
}
__device__ __forceinline__ void sp2(float e, float o, uint32_t& hw, uint32_t& lw) {
    uint32_t he = bfbits(e), ho = bfbits(o);
    float re = e - __uint_as_float(he);
    float ro = o - __uint_as_float(ho);
    hw = __byte_perm(he, ho, 0x7632);
    lw = __byte_perm(bfbits(re), bfbits(ro), 0x7632);
}
__device__ __forceinline__ void mma_bf16(float* c, uint32_t a0, uint32_t a1,
                                         uint32_t a2, uint32_t a3,
                                         uint32_t b0, uint32_t b1) {
    asm volatile(
        "mma.sync.aligned.m16n8k16.row.col.f32.bf16.bf16.f32 "
        "{%0,%1,%2,%3}, {%4,%5,%6,%7}, {%8,%9}, {%0,%1,%2,%3};"
        : "+f"(c[0]), "+f"(c[1]), "+f"(c[2]), "+f"(c[3])
        : "r"(a0), "r"(a1), "r"(a2), "r"(a3), "r"(b0), "r"(b1));
}
__device__ __forceinline__ uint32_t smem_u32(const void* p) {
    uint32_t a;
    asm("{ .reg .u64 t; cvta.to.shared.u64 t, %1; cvt.u32.u64 %0, t; }"
        : "=r"(a) : "l"(p));
    return a;
}
__device__ __forceinline__ void cpa16(uint32_t dst, const uint32_t* src) {
    asm volatile("cp.async.cg.shared.global [%0], [%1], 16;"
                 :: "r"(dst), "l"(src) : "memory");
}
__device__ __forceinline__ void cpa8(uint32_t dst, const uint32_t* src) {
    asm volatile("cp.async.ca.shared.global [%0], [%1], 8;"
                 :: "r"(dst), "l"(src) : "memory");
}
#define CP_COMMIT() asm volatile("cp.async.commit_group;" ::: "memory")

// ===========================================================================
// conversion kernels (merged)
// ===========================================================================
__device__ __forceinline__ void conv_b_body(const float* W, uint32_t* Wh,
                                            uint32_t* Wl, int N, int idx) {
    int k2 = idx / (N / 4), n4 = (idx % (N / 4)) * 4;
    const float* r0 = W + (size_t)(2 * k2) * N + n4;
    float4 a = *(const float4*)r0;
    float4 b = *(const float4*)(r0 + N);
    uint4 h, l;
    sp2(a.x, b.x, h.x, l.x); sp2(a.y, b.y, h.y, l.y);
    sp2(a.z, b.z, h.z, l.z); sp2(a.w, b.w, h.w, l.w);
    *(uint4*)(Wh + (size_t)k2 * N + n4) = h;
    *(uint4*)(Wl + (size_t)k2 * N + n4) = l;
}
__global__ __launch_bounds__(256) void conv_w(const float* __restrict__ Wkv,
                                              const float* __restrict__ Wq,
                                              const float* __restrict__ Wp) {
    int bx = blockIdx.x;
    if (bx < 1024)
        conv_b_body(Wkv, g_WkvH, g_WkvL, 2048, bx * 256 + threadIdx.x);
    else if (bx < 1536)
        conv_b_body(Wq, g_WqH, g_WqL, 1024, (bx - 1024) * 256 + threadIdx.x);
    else
        conv_b_body(Wp, g_WpH, g_WpL, 1024, (bx - 1536) * 256 + threadIdx.x);
}
__global__ __launch_bounds__(256) void conv_x(const float* __restrict__ enc,
                                              const float* __restrict__ inp) {
    int bx = blockIdx.x;
    const float* A = (bx < 2048) ? enc : inp;
    uint32_t* Ah = (bx < 2048) ? g_encH : g_inH;
    uint32_t* Al = (bx < 2048) ? g_encL : g_inL;
    int idx = (bx & 2047) * 256 + threadIdx.x;
    int m = idx >> 7, c8 = (idx & 127) * 8;
    float4 f0 = *(const float4*)(A + (size_t)m * 1024 + c8);
    float4 f1 = *(const float4*)(A + (size_t)m * 1024 + c8 + 4);
    uint4 h, l;
    sp2(f0.x, f0.y, h.x, l.x); sp2(f0.z, f0.w, h.y, l.y);
    sp2(f1.x, f1.y, h.z, l.z); sp2(f1.z, f1.w, h.w, l.w);
    *(uint4*)(Ah + (size_t)m * 512 + c8 / 2) = h;
    *(uint4*)(Al + (size_t)m * 512 + c8 / 2) = l;
}
__global__ __launch_bounds__(256) void conv_v() {
    int idx = blockIdx.x * 256 + threadIdx.x;
    int bt2 = idx >> 4;
    int c4  = (idx & 15) * 4;
    const float* src = g_V + (size_t)bt2 * 2 * HDIM + c4;
    float4 a = *(const float4*)src;
    float4 b = *(const float4*)(src + HDIM);
    uint4 h, l;
    sp2(a.x, b.x, h.x, l.x); sp2(a.y, b.y, h.y, l.y);
    sp2(a.z, b.z, h.z, l.z); sp2(a.w, b.w, h.w, l.w);
    *(uint4*)(g_Vh2 + (size_t)bt2 * HDIM + c4) = h;
    *(uint4*)(g_Vl2 + (size_t)bt2 * HDIM + c4) = l;
}
__global__ __launch_bounds__(256) void mask_scan(const unsigned char* __restrict__ mask) {
    const unsigned char* base = mask + (size_t)(blockIdx.x * 128) * T_LEN + blockIdx.y * 64;
    uint32_t m = 0;
    #pragma unroll
    for (int it = 0; it < 2; it++) {
        int idx = threadIdx.x + it * 256;
        int r = idx >> 2, c16 = (idx & 3) * 16;
        uint4 v = *(const uint4*)(base + (size_t)r * T_LEN + c16);
        m |= v.x | v.y | v.z | v.w;
    }
    int any = __syncthreads_or((int)m);
    if (threadIdx.x == 0) g_mflag[blockIdx.x * 32 + blockIdx.y] = any;
}

// ===========================================================================
// 3x-bf16 GEMM, cp.async pipeline: 3 stages x 2 K-chunks (k=32) per stage.
// One wait+barrier per 2 chunks. smem = 3*2*STG*4 = 125952 B, 1 CTA/SM.
// ===========================================================================
#define PADA 12
#define PADB 136
#define A_SZ (128*PADA)          /* 1536 */
#define B_SZ (8*PADB)            /* 1088 */
#define STG  (2*A_SZ + 2*B_SZ)   /* 5248 u32 per chunk */

template<int MODE>
__global__ __launch_bounds__(256) void mma_gemm(
    const uint32_t* __restrict__ Ahg, const uint32_t* __restrict__ Alg,
    const uint32_t* __restrict__ Bhg, const uint32_t* __restrict__ Blg,
    const float* __restrict__ bias, const float* __restrict__ u,
    float* __restrict__ out, int N)
{
    extern __shared__ uint32_t sm[];

    const int tid  = threadIdx.x;
    const int wid  = tid >> 5, lane = tid & 31;
    const int g    = lane >> 2, tg = lane & 3;
    const int wm   = wid >> 2,  wn = wid & 3;
    const int m0   = blockIdx.y * 128, n0 = blockIdx.x * 128;

    const int aRow = tid >> 2;          // 0..63
    const int aKp  = (tid & 3) * 2;     // kpair base 0,2,4,6
    const int bKp  = tid >> 5;          // kpair 0..7
    const int bCol = (tid & 31) * 4;    // 0..124

    const uint32_t smb = smem_u32(sm);

    // copy ONE K-chunk (8 kpairs) into chunk region at byte address cb
    #define GEMM_LOAD(cb, k2) do { \
        uint32_t aoff0 = (uint32_t)(aRow * PADA + aKp) * 4; \
        uint32_t aoff1 = (uint32_t)((aRow + 64) * PADA + aKp) * 4; \
        cpa8((cb) + aoff0,                    Ahg + (size_t)(m0 + aRow)      * 512 + (k2) + aKp); \
        cpa8((cb) + aoff1,                    Ahg + (size_t)(m0 + aRow + 64) * 512 + (k2) + aKp); \
        cpa8((cb) + A_SZ * 4 + aoff0,         Alg + (size_t)(m0 + aRow)      * 512 + (k2) + aKp); \
        cpa8((cb) + A_SZ * 4 + aoff1,         Alg + (size_t)(m0 + aRow + 64) * 512 + (k2) + aKp); \
        uint32_t boff = (uint32_t)(bKp * PADB + bCol) * 4; \
        cpa16((cb) + 2 * A_SZ * 4 + boff,            Bhg + (size_t)((k2) + bKp) * N + n0 + bCol); \
        cpa16((cb) + (2 * A_SZ + B_SZ) * 4 + boff,   Blg + (size_t)((k2) + bKp) * N + n0 + bCol); \
    } while (0)

    float acc[4][4][4] = {};

    // prologue: fill stages 0 and 1 (2 chunks each)
    GEMM_LOAD(smb,               0);
    GEMM_LOAD(smb + STG * 4,     8);
    CP_COMMIT();
    GEMM_LOAD(smb + 2 * STG * 4, 16);
    GEMM_LOAD(smb + 3 * STG * 4, 24);
    CP_COMMIT();

    const int NIT = 32;                 // 32 iterations x 2 chunks = 64 chunks
    int st = 0;
    for (int it = 0; it < NIT; it++) {
        if (it < NIT - 1) {
            asm volatile("cp.async.wait_group 1;" ::: "memory");
        } else {
            asm volatile("cp.async.wait_group 0;" ::: "memory");
        }
        __syncthreads();
        if (it + 2 < NIT) {
            int st2 = (st + 2 >= 3) ? st - 1 : st + 2;
            uint32_t sb2 = smb + st2 * (2 * STG * 4);
            GEMM_LOAD(sb2,           (it + 2) * 16);
            GEMM_LOAD(sb2 + STG * 4, (it + 2) * 16 + 8);
            CP_COMMIT();
        }

        #pragma unroll
        for (int half = 0; half < 2; half++) {
            uint32_t* Ah = sm + st * (2 * STG) + half * STG;
            uint32_t* Al = Ah + A_SZ;
            uint32_t* Bh = Ah + 2 * A_SZ;
            uint32_t* Bl = Ah + 2 * A_SZ + B_SZ;

            uint32_t ah[4][4], al4[4][4];
            #pragma unroll
            for (int mt = 0; mt < 4; mt++) {
                int r = wm * 64 + mt * 16 + g;
                ah[mt][0]  = Ah[r * PADA + tg];
                ah[mt][1]  = Ah[(r + 8) * PADA + tg];
                ah[mt][2]  = Ah[r * PADA + tg + 4];
                ah[mt][3]  = Ah[(r + 8) * PADA + tg + 4];
                al4[mt][0] = Al[r * PADA + tg];
                al4[mt][1] = Al[(r + 8) * PADA + tg];
                al4[mt][2] = Al[r * PADA + tg + 4];
                al4[mt][3] = Al[(r + 8) * PADA + tg + 4];
            }
            uint32_t bh[4][2], bl4r[4][2];
            #pragma unroll
            for (int nt = 0; nt < 4; nt++) {
                int c = wn * 32 + nt * 8 + g;
                bh[nt][0]   = Bh[tg * PADB + c];
                bh[nt][1]   = Bh[(tg + 4) * PADB + c];
                bl4r[nt][0] = Bl[tg * PADB + c];
                bl4r[nt][1] = Bl[(tg + 4) * PADB + c];
            }
            #pragma unroll
            for (int mt = 0; mt < 4; mt++)
                #pragma unroll
                for (int nt = 0; nt < 4; nt++) {
                    float* c = acc[mt][nt];
                    mma_bf16(c, ah[mt][0], ah[mt][1], ah[mt][2], ah[mt][3],
                                bh[nt][0], bh[nt][1]);
                    mma_bf16(c, ah[mt][0], ah[mt][1], ah[mt][2], ah[mt][3],
                                bl4r[nt][0], bl4r[nt][1]);
                    mma_bf16(c, al4[mt][0], al4[mt][1], al4[mt][2], al4[mt][3],
                                bh[nt][0], bh[nt][1]);
                }
        }

        st = (st + 1 >= 3) ? 0 : st + 1;
    }
    #undef GEMM_LOAD

    // ---------------- epilogue ------------------------------------------
    #pragma unroll
    for (int mt = 0; mt < 4; mt++) {
        #pragma unroll
        for (int nt = 0; nt < 4; nt++) {
            int n  = n0 + wn * 32 + nt * 8 + tg * 2;
            int mA = m0 + wm * 64 + mt * 16 + g;
            float bs0 = __ldg(bias + n), bs1 = __ldg(bias + n + 1);
            float v00 = acc[mt][nt][0] + bs0;
            float v01 = acc[mt][nt][1] + bs1;
            float v10 = acc[mt][nt][2] + bs0;
            float v11 = acc[mt][nt][3] + bs1;
            int t0 = mA >> 1, bb = mA & 1;
            int t1 = (mA + 8) >> 1;
            if (MODE == 0) {
                if (n < HD) {
                    int h = n >> 6, d2 = (n & 63) >> 1;
                    size_t base = ((size_t)(bb * HEADS + h)) * 32 * T_LEN + (size_t)d2 * T_LEN;
                    uint32_t hw, lw;
                    sp2(v00, v01, hw, lw);
                    g_KhT[base + t0] = hw;
                    g_KlT[base + t0] = lw;
                    sp2(v10, v11, hw, lw);
                    g_KhT[base + t1] = hw;
                    g_KlT[base + t1] = lw;
                } else {
                    int nn = n - HD;
                    int h = nn >> 6, d = nn & 63;
                    size_t base = (((size_t)(bb * HEADS + h)) * T_LEN) * HDIM + d;
                    g_V[base + (size_t)t0 * HDIM]     = v00;
                    g_V[base + (size_t)t0 * HDIM + 1] = v01;
                    g_V[base + (size_t)t1 * HDIM]     = v10;
                    g_V[base + (size_t)t1 * HDIM + 1] = v11;
                }
            } else if (MODE == 1) {
                float u0 = __ldg(u + n), u1 = __ldg(u + n + 1);
                int h = n >> 6, d2 = (n & 63) >> 1;
                size_t base = ((size_t)(bb * HEADS + h)) * S_LEN;
                uint32_t hw, lw;
                sp2(v00 + u0, v01 + u1, hw, lw);
                g_Qh[(base + t0) * 32 + d2] = hw;
                g_Ql[(base + t0) * 32 + d2] = lw;
                sp2(v10 + u0, v11 + u1, hw, lw);
                g_Qh[(base + t1) * 32 + d2] = hw;
                g_Ql[(base + t1) * 32 + d2] = lw;
            } else {
                out[(size_t)mA * EDIM + n]           = v00;
                out[(size_t)mA * EDIM + n + 1]       = v01;
                out[(size_t)(mA + 8) * EDIM + n]     = v10;
                out[(size_t)(mA + 8) * EDIM + n + 1] = v11;
            }
        }
    }
}

// ===========================================================================
// Flash attention, 3x-bf16, cp.async double-buffered K/V (unchanged R11).
// ===========================================================================
#define PADT 72
#define PADP 36
#define KVBUF (32*PADT)

__global__ __launch_bounds__(256, 2) void attn_bf16(const unsigned char* __restrict__ mask)
{
    extern __shared__ uint32_t smu[];
    uint32_t* Ph = smu + 8 * KVBUF;
    uint32_t* Pl = Ph + 128 * PADP;

    const int bh = blockIdx.y;
    const int b  = bh >> 4;
    const int h  = bh & 15;
    const int s0 = blockIdx.x * 128;
    const int tid = threadIdx.x;
    const int wid = tid >> 5, lane = tid & 31;
    const int g   = lane >> 2, tg = lane & 3;
    const int rowA = wid * 16 + g;

    const uint32_t* KhTg = g_KhT + (size_t)bh * 32 * T_LEN;
    const uint32_t* KlTg = g_KlT + (size_t)bh * 32 * T_LEN;
    const uint32_t* Vh2g = g_Vh2 + (size_t)bh * (T_LEN / 2) * HDIM;
    const uint32_t* Vl2g = g_Vl2 + (size_t)bh * (T_LEN / 2) * HDIM;

    const uint32_t smb = smem_u32(smu);
    const int lr  = tid >> 4;
    const int lc4 = (tid & 15) * 4;

    uint32_t qh[4][4], ql[4][4];
    {
        const uint32_t* qh0 = g_Qh + ((size_t)bh * S_LEN + s0 + rowA) * 32;
        const uint32_t* qh1 = qh0 + 8 * 32;
        const uint32_t* ql0 = g_Ql + ((size_t)bh * S_LEN + s0 + rowA) * 32;
        const uint32_t* ql1 = ql0 + 8 * 32;
        #pragma unroll
        for (int ks = 0; ks < 4; ks++) {
            qh[ks][0] = qh0[ks * 8 + tg];
            qh[ks][1] = qh1[ks * 8 + tg];
            qh[ks][2] = qh0[ks * 8 + tg + 4];
            qh[ks][3] = qh1[ks * 8 + tg + 4];
            ql[ks][0] = ql0[ks * 8 + tg];
            ql[ks][1] = ql1[ks * 8 + tg];
            ql[ks][2] = ql0[ks * 8 + tg + 4];
            ql[ks][3] = ql1[ks * 8 + tg + 4];
        }
    }

    #define LOAD_KV(bf, j0) do { \
        uint32_t kbp = smb + (bf) * (4 * KVBUF * 4); \
        int r0_ = lr, r1_ = lr + 16; \
        uint32_t off0 = (uint32_t)(r0_ * PADT + lc4) * 4; \
        uint32_t off1 = (uint32_t)(r1_ * PADT + lc4) * 4; \
        cpa16(kbp + off0,                 KhTg + (size_t)r0_ * T_LEN + (j0) + lc4); \
        cpa16(kbp + off1,                 KhTg + (size_t)r1_ * T_LEN + (j0) + lc4); \
        cpa16(kbp + KVBUF * 4 + off0,     KlTg + (size_t)r0_ * T_LEN + (j0) + lc4); \
        cpa16(kbp + KVBUF * 4 + off1,     KlTg + (size_t)r1_ * T_LEN + (j0) + lc4); \
        cpa16(kbp + 2 * KVBUF * 4 + off0, Vh2g + (size_t)(((j0) >> 1) + r0_) * HDIM + lc4); \
        cpa16(kbp + 2 * KVBUF * 4 + off1, Vh2g + (size_t)(((j0) >> 1) + r1_) * HDIM + lc4); \
        cpa16(kbp + 3 * KVBUF * 4 + off0, Vl2g + (size_t)(((j0) >> 1) + r0_) * HDIM + lc4); \
        cpa16(kbp + 3 * KVBUF * 4 + off1, Vl2g + (size_t)(((j0) >> 1) + r1_) * HDIM + lc4); \
    } while (0)

    float o[8][4] = {};
    float m0 = -1e30f, m1 = -1e30f, l0 = 0.f, l1 = 0.f;

    LOAD_KV(0, 0);
    CP_COMMIT();

    for (int jt = 0; jt < 32; jt++) {
        const int j0 = jt << 6;
        const int buf = jt & 1;
        if (jt < 31) {
            LOAD_KV(buf ^ 1, j0 + 64);
            CP_COMMIT();
            asm volatile("cp.async.wait_group 1;" ::: "memory");
        } else {
            asm volatile("cp.async.wait_group 0;" ::: "memory");
        }
        int any_mask = g_mflag[blockIdx.x * 32 + jt];
        __syncthreads();

        uint32_t* Kh = smu + buf * 4 * KVBUF;
        uint32_t* Kl = Kh + KVBUF;
        uint32_t* Vh = Kh + 2 * KVBUF;
        uint32_t* Vl = Kh + 3 * KVBUF;

        float sc[8][4] = {};
        #pragma unroll
        for (int ks = 0; ks < 4; ks++) {
            #pragma unroll
            for (int nt = 0; nt < 8; nt++) {
                int n = nt * 8 + g;
                uint32_t b0h = Kh[(ks * 8 + tg)     * PADT + n];
                uint32_t b1h = Kh[(ks * 8 + tg + 4) * PADT + n];
                uint32_t b0l = Kl[(ks * 8 + tg)     * PADT + n];
                uint32_t b1l = Kl[(ks * 8 + tg + 4) * PADT + n];
                mma_bf16(sc[nt], qh[ks][0], qh[ks][1], qh[ks][2], qh[ks][3], b0h, b1h);
                mma_bf16(sc[nt], qh[ks][0], qh[ks][1], qh[ks][2], qh[ks][3], b0l, b1l);
                mma_bf16(sc[nt], ql[ks][0], ql[ks][1], ql[ks][2], ql[ks][3], b0h, b1h);
            }
        }

        #pragma unroll
        for (int nt = 0; nt < 8; nt++) {
            sc[nt][0] *= 0.125f; sc[nt][1] *= 0.125f;
            sc[nt][2] *= 0.125f; sc[nt][3] *= 0.125f;
        }
        if (any_mask) {
            int sg0 = s0 + rowA, sg1 = sg0 + 8;
            #pragma unroll
            for (int nt = 0; nt < 8; nt++) {
                int cg = j0 + nt * 8 + tg * 2;
                const unsigned char* m0p = mask + (size_t)sg0 * T_LEN + cg;
                const unsigned char* m1p = mask + (size_t)sg1 * T_LEN + cg;
                if (m0p[0]) sc[nt][0] = -INFINITY;
                if (m0p[1]) sc[nt][1] = -INFINITY;
                if (m1p[0]) sc[nt][2] = -INFINITY;
                if (m1p[1]) sc[nt][3] = -INFINITY;
            }
        }

        float mx0 = -1e30f, mx1 = -1e30f;
        #pragma unroll
        for (int nt = 0; nt < 8; nt++) {
            mx0 = fmaxf(mx0, fmaxf(sc[nt][0], sc[nt][1]));
            mx1 = fmaxf(mx1, fmaxf(sc[nt][2], sc[nt][3]));
        }
        mx0 = fmaxf(mx0, __shfl_xor_sync(0xffffffffu, mx0, 1));
        mx0 = fmaxf(mx0, __shfl_xor_sync(0xffffffffu, mx0, 2));
        mx1 = fmaxf(mx1, __shfl_xor_sync(0xffffffffu, mx1, 1));
        mx1 = fmaxf(mx1, __shfl_xor_sync(0xffffffffu, mx1, 2));

        float mn0 = fmaxf(m0, mx0), mn1 = fmaxf(m1, mx1);
        float cr0 = __expf(m0 - mn0), cr1 = __expf(m1 - mn1);
        float ps0 = 0.f, ps1 = 0.f;
        #pragma unroll
        for (int nt = 0; nt < 8; nt++) {
            sc[nt][0] = __expf(sc[nt][0] - mn0);
            sc[nt][1] = __expf(sc[nt][1] - mn0);
            sc[nt][2] = __expf(sc[nt][2] - mn1);
            sc[nt][3] = __expf(sc[nt][3] - mn1);
            ps0 += sc[nt][0] + sc[nt][1];
            ps1 += sc[nt][2] + sc[nt][3];
        }
        ps0 += __shfl_xor_sync(0xffffffffu, ps0, 1);
        ps0 += __shfl_xor_sync(0xffffffffu, ps0, 2);
        ps1 += __shfl_xor_sync(0xffffffffu, ps1, 1);
        ps1 += __shfl_xor_sync(0xffffffffu, ps1, 2);
        l0 = l0 * cr0 + ps0; m0 = mn0;
        l1 = l1 * cr1 + ps1; m1 = mn1;
        #pragma unroll
        for (int nt = 0; nt < 8; nt++) {
            o[nt][0] *= cr0; o[nt][1] *= cr0;
            o[nt][2] *= cr1; o[nt][3] *= cr1;
        }

        #pragma unroll
        for (int nt = 0; nt < 8; nt++) {
            int c2 = nt * 4 + tg;
            uint32_t hw, lw;
            sp2(sc[nt][0], sc[nt][1], hw, lw);
            Ph[rowA * PADP + c2] = hw; Pl[rowA * PADP + c2] = lw;
            sp2(sc[nt][2], sc[nt][3], hw, lw);
            Ph[(rowA + 8) * PADP + c2] = hw; Pl[(rowA + 8) * PADP + c2] = lw;
        }
        __syncwarp();

        #pragma unroll
        for (int ks = 0; ks < 4; ks++) {
            uint32_t ah[4], al[4];
            ah[0] = Ph[ rowA      * PADP + ks * 8 + tg];
            ah[1] = Ph[(rowA + 8) * PADP + ks * 8 + tg];
            ah[2] = Ph[ rowA      * PADP + ks * 8 + tg + 4];
            ah[3] = Ph[(rowA + 8) * PADP + ks * 8 + tg + 4];
            al[0] = Pl[ rowA      * PADP + ks * 8 + tg];
            al[1] = Pl[(rowA + 8) * PADP + ks * 8 + tg];
            al[2] = Pl[ rowA      * PADP + ks * 8 + tg + 4];
            al[3] = Pl[(rowA + 8) * PADP + ks * 8 + tg + 4];
            #pragma unroll
            for (int nt = 0; nt < 8; nt++) {
                int n = nt * 8 + g;
                uint32_t b0h = Vh[(ks * 8 + tg)     * PADT + n];
                uint32_t b1h = Vh[(ks * 8 + tg + 4) * PADT + n];
                uint32_t b0l = Vl[(ks * 8 + tg)     * PADT + n];
                uint32_t b1l = Vl[(ks * 8 + tg + 4) * PADT + n];
                mma_bf16(o[nt], ah[0], ah[1], ah[2], ah[3], b0h, b1h);
                mma_bf16(o[nt], ah[0], ah[1], ah[2], ah[3], b0l, b1l);
                mma_bf16(o[nt], al[0], al[1], al[2], al[3], b0h, b1h);
            }
        }
        __syncthreads();
    }

    float i0 = 1.f / l0, i1 = 1.f / l1;
    int sg0 = s0 + rowA, sg1 = sg0 + 8;
    #pragma unroll
    for (int nt = 0; nt < 8; nt++) {
        int c2 = h * 32 + nt * 4 + tg;
        uint32_t hw, lw;
        sp2(o[nt][0] * i0, o[nt][1] * i0, hw, lw);
        g_AVh[((size_t)sg0 * BATCH + b) * 512 + c2] = hw;
        g_AVl[((size_t)sg0 * BATCH + b) * 512 + c2] = lw;
        sp2(o[nt][2] * i1, o[nt][3] * i1, hw, lw);
        g_AVh[((size_t)sg1 * BATCH + b) * 512 + c2] = hw;
        g_AVl[((size_t)sg1 * BATCH + b) * 512 + c2] = lw;
    }
}

// ---------------------------------------------------------------------------
extern "C" void kernel_launch(void* const* d_in, const int* in_sizes, int n_in,
                              void* d_out, int out_size)
{
    const float* inputs = (const float*)d_in[0];
    const float* enc    = (const float*)d_in[2];
    const float* u      = (const float*)d_in[3];
    const unsigned char* mask = (const unsigned char*)d_in[5];
    const float* Wkv = (const float*)d_in[6];
    const float* bkv = (const float*)d_in[7];
    const float* Wq  = (const float*)d_in[8];
    const float* bq  = (const float*)d_in[9];
    const float* Wp  = (const float*)d_in[10];
    const float* bp  = (const float*)d_in[11];
    float* out = (float*)d_out;

    uint32_t *encH, *encL, *inH, *inL, *wkvH, *wkvL, *wqH, *wqL, *wpH, *wpL, *avH, *avL;
    cudaGetSymbolAddress((void**)&encH, g_encH); cudaGetSymbolAddress((void**)&encL, g_encL);
    cudaGetSymbolAddress((void**)&inH,  g_inH);  cudaGetSymbolAddress((void**)&inL,  g_inL);
    cudaGetSymbolAddress((void**)&wkvH, g_WkvH); cudaGetSymbolAddress((void**)&wkvL, g_WkvL);
    cudaGetSymbolAddress((void**)&wqH,  g_WqH);  cudaGetSymbolAddress((void**)&wqL,  g_WqL);
    cudaGetSymbolAddress((void**)&wpH,  g_WpH);  cudaGetSymbolAddress((void**)&wpL,  g_WpL);
    cudaGetSymbolAddress((void**)&avH,  g_AVh);  cudaGetSymbolAddress((void**)&avL,  g_AVl);

    const int GSMEM = 3 * 2 * STG * 4;                     // 125952 B
    const int ASMEM = (8 * KVBUF + 2 * 128 * PADP) * 4;    // 110592 B
    cudaFuncSetAttribute(mma_gemm<0>, cudaFuncAttributeMaxDynamicSharedMemorySize, GSMEM);
    cudaFuncSetAttribute(mma_gemm<1>, cudaFuncAttributeMaxDynamicSharedMemorySize, GSMEM);
    cudaFuncSetAttribute(mma_gemm<2>, cudaFuncAttributeMaxDynamicSharedMemorySize, GSMEM);
    cudaFuncSetAttribute(attn_bf16,   cudaFuncAttributeMaxDynamicSharedMemorySize, ASMEM);

    dim3 blk(256);
    conv_w<<<2048, blk>>>(Wkv, Wq, Wp);
    conv_x<<<4096, blk>>>(enc, inputs);
    mask_scan<<<dim3(16, 32), blk>>>(mask);
    mma_gemm<0><<<dim3(16, 32), blk, GSMEM>>>(encH, encL, wkvH, wkvL, bkv, nullptr, nullptr, 2 * HD);
    conv_v<<<2048, blk>>>();
    mma_gemm<1><<<dim3(8, 32),  blk, GSMEM>>>(inH,  inL,  wqH,  wqL,  bq,  u,       nullptr, HD);
    attn_bf16<<<dim3(S_LEN / 128, BATCH * HEADS), blk, ASMEM>>>(mask);
    mma_gemm<2><<<dim3(8, 32),  blk, GSMEM>>>(avH, avL, wpH, wpL, bp, nullptr, out, HD);
}

// round 15
// speedup vs baseline: 1.0588x; 1.0588x over previous
#include <cuda_runtime.h>
#include <math.h>
#include <stdint.h>

#define S_LEN 2048
#define T_LEN 2048
#define BATCH 2
#define EDIM  1024
#define HEADS 16
#define HDIM  64
#define HD    (HEADS*HDIM)   /* 1024 */

// ---------------- scratch (static device globals; no allocation) ----------
__device__ uint32_t g_encH[4096*512], g_encL[4096*512];   // enc  (T*B, E/2)
__device__ uint32_t g_inH [4096*512], g_inL [4096*512];   // inp  (S*B, E/2)
__device__ uint32_t g_WkvH[512*2048], g_WkvL[512*2048];   // Wkv  (E/2, 2HD)
__device__ uint32_t g_WqH [512*1024], g_WqL [512*1024];   // Wq   (E/2, HD)
__device__ uint32_t g_WpH [512*1024], g_WpL [512*1024];   // Wp   (HD/2, E)
__device__ uint32_t g_KhT[BATCH*HEADS*32*T_LEN], g_KlT[BATCH*HEADS*32*T_LEN]; // (B,H,D/2,T)
__device__ uint32_t g_Qh[BATCH*HEADS*S_LEN*32], g_Ql[BATCH*HEADS*S_LEN*32];   // (B,H,S,D/2)
__device__ float    g_V [BATCH*HEADS*T_LEN*HDIM];                              // (B,H,T,D)
__device__ uint32_t g_Vh2[BATCH*HEADS*(T_LEN/2)*HDIM], g_Vl2[BATCH*HEADS*(T_LEN/2)*HDIM]; // (B,H,T/2,D)
__device__ uint32_t g_AVh[4096*512], g_AVl[4096*512];     // (S*B, HD/2)
__device__ int      g_mflag[16*32];                       // per (s-block, j-tile)

// ---------------- bf16 split helpers ---------------------------------------
__device__ __forceinline__ uint32_t bfbits(float x) {
    uint32_t u = __float_as_uint(x);
    return (u + 0x7FFFu + ((u >> 16) & 1u)) & 0xFFFF0000u;
}
__device__ __forceinline__ void sp2(float e, float o, uint32_t& hw, uint32_t& lw) {
    uint32_t he = bfbits(e), ho = bfbits(o);
    float re = e - __uint_as_float(he);
    float ro = o - __uint_as_float(ho);
    hw = __byte_perm(he, ho, 0x7632);
    lw = __byte_perm(bfbits(re), bfbits(ro), 0x7632);
}
__device__ __forceinline__ void mma_bf16(float* c, uint32_t a0, uint32_t a1,
                                         uint32_t a2, uint32_t a3,
                                         uint32_t b0, uint32_t b1) {
    asm volatile(
        "mma.sync.aligned.m16n8k16.row.col.f32.bf16.bf16.f32 "
        "{%0,%1,%2,%3}, {%4,%5,%6,%7}, {%8,%9}, {%0,%1,%2,%3};"
        : "+f"(c[0]), "+f"(c[1]), "+f"(c[2]), "+f"(c[3])
        : "r"(a0), "r"(a1), "r"(a2), "r"(a3), "r"(b0), "r"(b1));
}
__device__ __forceinline__ uint32_t smem_u32(const void* p) {
    uint32_t a;
    asm("{ .reg .u64 t; cvta.to.shared.u64 t, %1; cvt.u32.u64 %0, t; }"
        : "=r"(a) : "l"(p));
    return a;
}
__device__ __forceinline__ void cpa16(uint32_t dst, const uint32_t* src) {
    asm volatile("cp.async.cg.shared.global [%0], [%1], 16;"
                 :: "r"(dst), "l"(src) : "memory");
}
__device__ __forceinline__ void cpa8(uint32_t dst, const uint32_t* src) {
    asm volatile("cp.async.ca.shared.global [%0], [%1], 8;"
                 :: "r"(dst), "l"(src) : "memory");
}
#define CP_COMMIT() asm volatile("cp.async.commit_group;" ::: "memory")

// ===========================================================================
// conversion kernels
// ===========================================================================
__device__ __forceinline__ void conv_b_body(const float* W, uint32_t* Wh,
                                            uint32_t* Wl, int N, int idx) {
    int k2 = idx / (N / 4), n4 = (idx % (N / 4)) * 4;
    const float* r0 = W + (size_t)(2 * k2) * N + n4;
    float4 a = *(const float4*)r0;
    float4 b = *(const float4*)(r0 + N);
    uint4 h, l;
    sp2(a.x, b.x, h.x, l.x); sp2(a.y, b.y, h.y, l.y);
    sp2(a.z, b.z, h.z, l.z); sp2(a.w, b.w, h.w, l.w);
    *(uint4*)(Wh + (size_t)k2 * N + n4) = h;
    *(uint4*)(Wl + (size_t)k2 * N + n4) = l;
}
__global__ __launch_bounds__(256) void conv_w(const float* __restrict__ Wkv,
                                              const float* __restrict__ Wq,
                                              const float* __restrict__ Wp) {
    int bx = blockIdx.x;
    if (bx < 1024)
        conv_b_body(Wkv, g_WkvH, g_WkvL, 2048, bx * 256 + threadIdx.x);
    else if (bx < 1536)
        conv_b_body(Wq, g_WqH, g_WqL, 1024, (bx - 1024) * 256 + threadIdx.x);
    else
        conv_b_body(Wp, g_WpH, g_WpL, 1024, (bx - 1536) * 256 + threadIdx.x);
}
__global__ __launch_bounds__(256) void conv_x(const float* __restrict__ enc,
                                              const float* __restrict__ inp) {
    int bx = blockIdx.x;
    const float* A = (bx < 2048) ? enc : inp;
    uint32_t* Ah = (bx < 2048) ? g_encH : g_inH;
    uint32_t* Al = (bx < 2048) ? g_encL : g_inL;
    int idx = (bx & 2047) * 256 + threadIdx.x;
    int m = idx >> 7, c8 = (idx & 127) * 8;
    float4 f0 = *(const float4*)(A + (size_t)m * 1024 + c8);
    float4 f1 = *(const float4*)(A + (size_t)m * 1024 + c8 + 4);
    uint4 h, l;
    sp2(f0.x, f0.y, h.x, l.x); sp2(f0.z, f0.w, h.y, l.y);
    sp2(f1.x, f1.y, h.z, l.z); sp2(f1.z, f1.w, h.w, l.w);
    *(uint4*)(Ah + (size_t)m * 512 + c8 / 2) = h;
    *(uint4*)(Al + (size_t)m * 512 + c8 / 2) = l;
}
__global__ __launch_bounds__(256) void conv_v() {
    int idx = blockIdx.x * 256 + threadIdx.x;
    int bt2 = idx >> 4;
    int c4  = (idx & 15) * 4;
    const float* src = g_V + (size_t)bt2 * 2 * HDIM + c4;
    float4 a = *(const float4*)src;
    float4 b = *(const float4*)(src + HDIM);
    uint4 h, l;
    sp2(a.x, b.x, h.x, l.x); sp2(a.y, b.y, h.y, l.y);
    sp2(a.z, b.z, h.z, l.z); sp2(a.w, b.w, h.w, l.w);
    *(uint4*)(g_Vh2 + (size_t)bt2 * HDIM + c4) = h;
    *(uint4*)(g_Vl2 + (size_t)bt2 * HDIM + c4) = l;
}
__global__ __launch_bounds__(256) void mask_scan(const unsigned char* __restrict__ mask) {
    const unsigned char* base = mask + (size_t)(blockIdx.x * 128) * T_LEN + blockIdx.y * 64;
    uint32_t m = 0;
    #pragma unroll
    for (int it = 0; it < 2; it++) {
        int idx = threadIdx.x + it * 256;
        int r = idx >> 2, c16 = (idx & 3) * 16;
        uint4 v = *(const uint4*)(base + (size_t)r * T_LEN + c16);
        m |= v.x | v.y | v.z | v.w;
    }
    int any = __syncthreads_or((int)m);
    if (threadIdx.x == 0) g_mflag[blockIdx.x * 32 + blockIdx.y] = any;
}

// ===========================================================================
// 3x-bf16 GEMM core: cp.async 3-stage x 1-chunk pipeline (R12 config).
// A smem [m][kpair] pad 12; B smem [kpair][n] pad 136. 63KB -> 2 CTA/SM.
// ===========================================================================
#define PADA 12
#define PADB 136
#define A_SZ (128*PADA)          /* 1536 */
#define B_SZ (8*PADB)            /* 1088 */
#define STG  (2*A_SZ + 2*B_SZ)   /* 5248 u32 per stage */

template<int MODE>
__device__ __forceinline__ void gemm_core(
    const float* __restrict__ bias, const float* __restrict__ u,
    float* __restrict__ out, int m0, int n0, uint32_t* sm)
{
    constexpr int N = (MODE == 0) ? 2048 : 1024;
    const uint32_t* Ahg = (MODE == 0) ? g_encH : (MODE == 1) ? g_inH : g_AVh;
    const uint32_t* Alg = (MODE == 0) ? g_encL : (MODE == 1) ? g_inL : g_AVl;
    const uint32_t* Bhg = (MODE == 0) ? g_WkvH : (MODE == 1) ? g_WqH : g_WpH;
    const uint32_t* Blg = (MODE == 0) ? g_WkvL : (MODE == 1) ? g_WqL : g_WpL;

    const int tid  = threadIdx.x;
    const int wid  = tid >> 5, lane = tid & 31;
    const int g    = lane >> 2, tg = lane & 3;
    const int wm   = wid >> 2,  wn = wid & 3;

    const int aRow = tid >> 2;          // 0..63
    const int aKp  = (tid & 3) * 2;     // kpair base 0,2,4,6
    const int bKp  = tid >> 5;          // kpair 0..7
    const int bCol = (tid & 31) * 4;    // 0..124

    const uint32_t smb = smem_u32(sm);

    #define GEMM_LOAD(st, k2) do { \
        uint32_t sb = smb + (st) * (STG * 4); \
        uint32_t aoff0 = (uint32_t)(aRow * PADA + aKp) * 4; \
        uint32_t aoff1 = (uint32_t)((aRow + 64) * PADA + aKp) * 4; \
        cpa8(sb + aoff0,                    Ahg + (size_t)(m0 + aRow)      * 512 + (k2) + aKp); \
        cpa8(sb + aoff1,                    Ahg + (size_t)(m0 + aRow + 64) * 512 + (k2) + aKp); \
        cpa8(sb + A_SZ * 4 + aoff0,         Alg + (size_t)(m0 + aRow)      * 512 + (k2) + aKp); \
        cpa8(sb + A_SZ * 4 + aoff1,         Alg + (size_t)(m0 + aRow + 64) * 512 + (k2) + aKp); \
        uint32_t boff = (uint32_t)(bKp * PADB + bCol) * 4; \
        cpa16(sb + 2 * A_SZ * 4 + boff,            Bhg + (size_t)((k2) + bKp) * N + n0 + bCol); \
        cpa16(sb + (2 * A_SZ + B_SZ) * 4 + boff,   Blg + (size_t)((k2) + bKp) * N + n0 + bCol); \
    } while (0)

    float acc[4][4][4] = {};

    GEMM_LOAD(0, 0); CP_COMMIT();
    GEMM_LOAD(1, 8); CP_COMMIT();

    const int NKB = 64;
    int st = 0;
    for (int kb = 0; kb < NKB; kb++) {
        if (kb < NKB - 1) {
            asm volatile("cp.async.wait_group 1;" ::: "memory");
        } else {
            asm volatile("cp.async.wait_group 0;" ::: "memory");
        }
        __syncthreads();
        if (kb + 2 < NKB) {
            int st2 = (st + 2 >= 3) ? st - 1 : st + 2;
            GEMM_LOAD(st2, (kb + 2) * 8);
            CP_COMMIT();
        }

        uint32_t* Ah = sm + st * STG;
        uint32_t* Al = Ah + A_SZ;
        uint32_t* Bh = Ah + 2 * A_SZ;
        uint32_t* Bl = Ah + 2 * A_SZ + B_SZ;

        uint32_t ah[4][4], al4[4][4];
        #pragma unroll
        for (int mt = 0; mt < 4; mt++) {
            int r = wm * 64 + mt * 16 + g;
            ah[mt][0]  = Ah[r * PADA + tg];
            ah[mt][1]  = Ah[(r + 8) * PADA + tg];
            ah[mt][2]  = Ah[r * PADA + tg + 4];
            ah[mt][3]  = Ah[(r + 8) * PADA + tg + 4];
            al4[mt][0] = Al[r * PADA + tg];
            al4[mt][1] = Al[(r + 8) * PADA + tg];
            al4[mt][2] = Al[r * PADA + tg + 4];
            al4[mt][3] = Al[(r + 8) * PADA + tg + 4];
        }
        uint32_t bh[4][2], bl4r[4][2];
        #pragma unroll
        for (int nt = 0; nt < 4; nt++) {
            int c = wn * 32 + nt * 8 + g;
            bh[nt][0]   = Bh[tg * PADB + c];
            bh[nt][1]   = Bh[(tg + 4) * PADB + c];
            bl4r[nt][0] = Bl[tg * PADB + c];
            bl4r[nt][1] = Bl[(tg + 4) * PADB + c];
        }
        #pragma unroll
        for (int mt = 0; mt < 4; mt++)
            #pragma unroll
            for (int nt = 0; nt < 4; nt++) {
                float* c = acc[mt][nt];
                mma_bf16(c, ah[mt][0], ah[mt][1], ah[mt][2], ah[mt][3],
                            bh[nt][0], bh[nt][1]);
                mma_bf16(c, ah[mt][0], ah[mt][1], ah[mt][2], ah[mt][3],
                            bl4r[nt][0], bl4r[nt][1]);
                mma_bf16(c, al4[mt][0], al4[mt][1], al4[mt][2], al4[mt][3],
                            bh[nt][0], bh[nt][1]);
            }

        st = (st + 1 >= 3) ? 0 : st + 1;
    }
    #undef GEMM_LOAD

    // ---------------- epilogue ------------------------------------------
    #pragma unroll
    for (int mt = 0; mt < 4; mt++) {
        #pragma unroll
        for (int nt = 0; nt < 4; nt++) {
            int n  = n0 + wn * 32 + nt * 8 + tg * 2;
            int mA = m0 + wm * 64 + mt * 16 + g;
            float bs0 = __ldg(bias + n), bs1 = __ldg(bias + n + 1);
            float v00 = acc[mt][nt][0] + bs0;
            float v01 = acc[mt][nt][1] + bs1;
            float v10 = acc[mt][nt][2] + bs0;
            float v11 = acc[mt][nt][3] + bs1;
            int t0 = mA >> 1, bb = mA & 1;
            int t1 = (mA + 8) >> 1;
            if (MODE == 0) {
                if (n < HD) {
                    int h = n >> 6, d2 = (n & 63) >> 1;
                    size_t base = ((size_t)(bb * HEADS + h)) * 32 * T_LEN + (size_t)d2 * T_LEN;
                    uint32_t hw, lw;
                    sp2(v00, v01, hw, lw);
                    g_KhT[base + t0] = hw;
                    g_KlT[base + t0] = lw;
                    sp2(v10, v11, hw, lw);
                    g_KhT[base + t1] = hw;
                    g_KlT[base + t1] = lw;
                } else {
                    int nn = n - HD;
                    int h = nn >> 6, d = nn & 63;
                    size_t base = (((size_t)(bb * HEADS + h)) * T_LEN) * HDIM + d;
                    g_V[base + (size_t)t0 * HDIM]     = v00;
                    g_V[base + (size_t)t0 * HDIM + 1] = v01;
                    g_V[base + (size_t)t1 * HDIM]     = v10;
                    g_V[base + (size_t)t1 * HDIM + 1] = v11;
                }
            } else if (MODE == 1) {
                float u0 = __ldg(u + n), u1 = __ldg(u + n + 1);
                int h = n >> 6, d2 = (n & 63) >> 1;
                size_t base = ((size_t)(bb * HEADS + h)) * S_LEN;
                uint32_t hw, lw;
                sp2(v00 + u0, v01 + u1, hw, lw);
                g_Qh[(base + t0) * 32 + d2] = hw;
                g_Ql[(base + t0) * 32 + d2] = lw;
                sp2(v10 + u0, v11 + u1, hw, lw);
                g_Qh[(base + t1) * 32 + d2] = hw;
                g_Ql[(base + t1) * 32 + d2] = lw;
            } else {
                out[(size_t)mA * EDIM + n]           = v00;
                out[(size_t)mA * EDIM + n + 1]       = v01;
                out[(size_t)(mA + 8) * EDIM + n]     = v10;
                out[(size_t)(mA + 8) * EDIM + n + 1] = v11;
            }
        }
    }
}

// merged kv + q projection: blocks [0,512) -> kv, [512,768) -> q
__global__ __launch_bounds__(256, 2) void proj_gemm(
    const float* __restrict__ bkv, const float* __restrict__ bq,
    const float* __restrict__ u)
{
    extern __shared__ uint32_t sm[];
    int bx = blockIdx.x;
    if (bx < 512) {
        gemm_core<0>(bkv, nullptr, nullptr, (bx >> 4) * 128, (bx & 15) * 128, sm);
    } else {
        int i = bx - 512;
        gemm_core<1>(bq, u, nullptr, (i >> 3) * 128, (i & 7) * 128, sm);
    }
}

__global__ __launch_bounds__(256, 2) void out_gemm(
    const float* __restrict__ bp, float* __restrict__ out)
{
    extern __shared__ uint32_t sm[];
    gemm_core<2>(bp, nullptr, out, (blockIdx.x >> 3) * 128, (blockIdx.x & 7) * 128, sm);
}

// ===========================================================================
// Flash attention, 3x-bf16, cp.async double-buffered K/V, ONE barrier/tile.
// ===========================================================================
#define PADT 72
#define PADP 36
#define KVBUF (32*PADT)

__global__ __launch_bounds__(256, 2) void attn_bf16(const unsigned char* __restrict__ mask)
{
    extern __shared__ uint32_t smu[];
    uint32_t* Ph = smu + 8 * KVBUF;
    uint32_t* Pl = Ph + 128 * PADP;

    const int bh = blockIdx.y;
    const int b  = bh >> 4;
    const int h  = bh & 15;
    const int s0 = blockIdx.x * 128;
    const int tid = threadIdx.x;
    const int wid = tid >> 5, lane = tid & 31;
    const int g   = lane >> 2, tg = lane & 3;
    const int rowA = wid * 16 + g;

    const uint32_t* KhTg = g_KhT + (size_t)bh * 32 * T_LEN;
    const uint32_t* KlTg = g_KlT + (size_t)bh * 32 * T_LEN;
    const uint32_t* Vh2g = g_Vh2 + (size_t)bh * (T_LEN / 2) * HDIM;
    const uint32_t* Vl2g = g_Vl2 + (size_t)bh * (T_LEN / 2) * HDIM;

    const uint32_t smb = smem_u32(smu);
    const int lr  = tid >> 4;
    const int lc4 = (tid & 15) * 4;

    uint32_t qh[4][4], ql[4][4];
    {
        const uint32_t* qh0 = g_Qh + ((size_t)bh * S_LEN + s0 + rowA) * 32;
        const uint32_t* qh1 = qh0 + 8 * 32;
        const uint32_t* ql0 = g_Ql + ((size_t)bh * S_LEN + s0 + rowA) * 32;
        const uint32_t* ql1 = ql0 + 8 * 32;
        #pragma unroll
        for (int ks = 0; ks < 4; ks++) {
            qh[ks][0] = qh0[ks * 8 + tg];
            qh[ks][1] = qh1[ks * 8 + tg];
            qh[ks][2] = qh0[ks * 8 + tg + 4];
            qh[ks][3] = qh1[ks * 8 + tg + 4];
            ql[ks][0] = ql0[ks * 8 + tg];
            ql[ks][1] = ql1[ks * 8 + tg];
            ql[ks][2] = ql0[ks * 8 + tg + 4];
            ql[ks][3] = ql1[ks * 8 + tg + 4];
        }
    }

    #define LOAD_KV(bf, j0) do { \
        uint32_t kbp = smb + (bf) * (4 * KVBUF * 4); \
        int r0_ = lr, r1_ = lr + 16; \
        uint32_t off0 = (uint32_t)(r0_ * PADT + lc4) * 4; \
        uint32_t off1 = (uint32_t)(r1_ * PADT + lc4) * 4; \
        cpa16(kbp + off0,                 KhTg + (size_t)r0_ * T_LEN + (j0) + lc4); \
        cpa16(kbp + off1,                 KhTg + (size_t)r1_ * T_LEN + (j0) + lc4); \
        cpa16(kbp + KVBUF * 4 + off0,     KlTg + (size_t)r0_ * T_LEN + (j0) + lc4); \
        cpa16(kbp + KVBUF * 4 + off1,     KlTg + (size_t)r1_ * T_LEN + (j0) + lc4); \
        cpa16(kbp + 2 * KVBUF * 4 + off0, Vh2g + (size_t)(((j0) >> 1) + r0_) * HDIM + lc4); \
        cpa16(kbp + 2 * KVBUF * 4 + off1, Vh2g + (size_t)(((j0) >> 1) + r1_) * HDIM + lc4); \
        cpa16(kbp + 3 * KVBUF * 4 + off0, Vl2g + (size_t)(((j0) >> 1) + r0_) * HDIM + lc4); \
        cpa16(kbp + 3 * KVBUF * 4 + off1, Vl2g + (size_t)(((j0) >> 1) + r1_) * HDIM + lc4); \
    } while (0)

    float o[8][4] = {};
    float m0 = -1e30f, m1 = -1e30f, l0 = 0.f, l1 = 0.f;

    LOAD_KV(0, 0);
    CP_COMMIT();

    for (int jt = 0; jt < 32; jt++) {
        const int j0 = jt << 6;
        const int buf = jt & 1;

        // wait for this tile's data; barrier doubles as "previous compute done"
        asm volatile("cp.async.wait_group 0;" ::: "memory");
        int any_mask = g_mflag[blockIdx.x * 32 + jt];
        __syncthreads();

        // prefetch next tile into the buffer nobody reads this iteration
        if (jt < 31) {
            LOAD_KV(buf ^ 1, j0 + 64);
            CP_COMMIT();
        }

        uint32_t* Kh = smu + buf * 4 * KVBUF;
        uint32_t* Kl = Kh + KVBUF;
        uint32_t* Vh = Kh + 2 * KVBUF;
        uint32_t* Vl = Kh + 3 * KVBUF;

        float sc[8][4] = {};
        #pragma unroll
        for (int ks = 0; ks < 4; ks++) {
            #pragma unroll
            for (int nt = 0; nt < 8; nt++) {
                int n = nt * 8 + g;
                uint32_t b0h = Kh[(ks * 8 + tg)     * PADT + n];
                uint32_t b1h = Kh[(ks * 8 + tg + 4) * PADT + n];
                uint32_t b0l = Kl[(ks * 8 + tg)     * PADT + n];
                uint32_t b1l = Kl[(ks * 8 + tg + 4) * PADT + n];
                mma_bf16(sc[nt], qh[ks][0], qh[ks][1], qh[ks][2], qh[ks][3], b0h, b1h);
                mma_bf16(sc[nt], qh[ks][0], qh[ks][1], qh[ks][2], qh[ks][3], b0l, b1l);
                mma_bf16(sc[nt], ql[ks][0], ql[ks][1], ql[ks][2], ql[ks][3], b0h, b1h);
            }
        }

        #pragma unroll
        for (int nt = 0; nt < 8; nt++) {
            sc[nt][0] *= 0.125f; sc[nt][1] *= 0.125f;
            sc[nt][2] *= 0.125f; sc[nt][3] *= 0.125f;
        }
        if (any_mask) {
            int sg0 = s0 + rowA, sg1 = sg0 + 8;
            #pragma unroll
            for (int nt = 0; nt < 8; nt++) {
                int cg = j0 + nt * 8 + tg * 2;
                const unsigned char* m0p = mask + (size_t)sg0 * T_LEN + cg;
                const unsigned char* m1p = mask + (size_t)sg1 * T_LEN + cg;
                if (m0p[0]) sc[nt][0] = -INFINITY;
                if (m0p[1]) sc[nt][1] = -INFINITY;
                if (m1p[0]) sc[nt][2] = -INFINITY;
                if (m1p[1]) sc[nt][3] = -INFINITY;
            }
        }

        float mx0 = -1e30f, mx1 = -1e30f;
        #pragma unroll
        for (int nt = 0; nt < 8; nt++) {
            mx0 = fmaxf(mx0, fmaxf(sc[nt][0], sc[nt][1]));
            mx1 = fmaxf(mx1, fmaxf(sc[nt][2], sc[nt][3]));
        }
        mx0 = fmaxf(mx0, __shfl_xor_sync(0xffffffffu, mx0, 1));
        mx0 = fmaxf(mx0, __shfl_xor_sync(0xffffffffu, mx0, 2));
        mx1 = fmaxf(mx1, __shfl_xor_sync(0xffffffffu, mx1, 1));
        mx1 = fmaxf(mx1, __shfl_xor_sync(0xffffffffu, mx1, 2));

        float mn0 = fmaxf(m0, mx0), mn1 = fmaxf(m1, mx1);
        float cr0 = __expf(m0 - mn0), cr1 = __expf(m1 - mn1);
        float ps0 = 0.f, ps1 = 0.f;
        #pragma unroll
        for (int nt = 0; nt < 8; nt++) {
            sc[nt][0] = __expf(sc[nt][0] - mn0);
            sc[nt][1] = __expf(sc[nt][1] - mn0);
            sc[nt][2] = __expf(sc[nt][2] - mn1);
            sc[nt][3] = __expf(sc[nt][3] - mn1);
            ps0 += sc[nt][0] + sc[nt][1];
            ps1 += sc[nt][2] + sc[nt][3];
        }
        ps0 += __shfl_xor_sync(0xffffffffu, ps0, 1);
        ps0 += __shfl_xor_sync(0xffffffffu, ps0, 2);
        ps1 += __shfl_xor_sync(0xffffffffu, ps1, 1);
        ps1 += __shfl_xor_sync(0xffffffffu, ps1, 2);
        l0 = l0 * cr0 + ps0; m0 = mn0;
        l1 = l1 * cr1 + ps1; m1 = mn1;
        #pragma unroll
        for (int nt = 0; nt < 8; nt++) {
            o[nt][0] *= cr0; o[nt][1] *= cr0;
            o[nt][2] *= cr1; o[nt][3] *= cr1;
        }

        #pragma unroll
        for (int nt = 0; nt < 8; nt++) {
            int c2 = nt * 4 + tg;
            uint32_t hw, lw;
            sp2(sc[nt][0], sc[nt][1], hw, lw);
            Ph[rowA * PADP + c2] = hw; Pl[rowA * PADP + c2] = lw;
            sp2(sc[nt][2], sc[nt][3], hw, lw);
            Ph[(rowA + 8) * PADP + c2] = hw; Pl[(rowA + 8) * PADP + c2] = lw;
        }
        __syncwarp();

        #pragma unroll
        for (int ks = 0; ks < 4; ks++) {
            uint32_t ah[4], al[4];
            ah[0] = Ph[ rowA      * PADP + ks * 8 + tg];
            ah[1] = Ph[(rowA + 8) * PADP + ks * 8 + tg];
            ah[2] = Ph[ rowA      * PADP + ks * 8 + tg + 4];
            ah[3] = Ph[(rowA + 8) * PADP + ks * 8 + tg + 4];
            al[0] = Pl[ rowA      * PADP + ks * 8 + tg];
            al[1] = Pl[(rowA + 8) * PADP + ks * 8 + tg];
            al[2] = Pl[ rowA      * PADP + ks * 8 + tg + 4];
            al[3] = Pl[(rowA + 8) * PADP + ks * 8 + tg + 4];
            #pragma unroll
            for (int nt = 0; nt < 8; nt++) {
                int n = nt * 8 + g;
                uint32_t b0h = Vh[(ks * 8 + tg)     * PADT + n];
                uint32_t b1h = Vh[(ks * 8 + tg + 4) * PADT + n];
                uint32_t b0l = Vl[(ks * 8 + tg)     * PADT + n];
                uint32_t b1l = Vl[(ks * 8 + tg + 4) * PADT + n];
                mma_bf16(o[nt], ah[0], ah[1], ah[2], ah[3], b0h, b1h);
                mma_bf16(o[nt], ah[0], ah[1], ah[2], ah[3], b0l, b1l);
                mma_bf16(o[nt], al[0], al[1], al[2], al[3], b0h, b1h);
            }
        }
    }

    float i0 = 1.f / l0, i1 = 1.f / l1;
    int sg0 = s0 + rowA, sg1 = sg0 + 8;
    #pragma unroll
    for (int nt = 0; nt < 8; nt++) {
        int c2 = h * 32 + nt * 4 + tg;
        uint32_t hw, lw;
        sp2(o[nt][0] * i0, o[nt][1] * i0, hw, lw);
        g_AVh[((size_t)sg0 * BATCH + b) * 512 + c2] = hw;
        g_AVl[((size_t)sg0 * BATCH + b) * 512 + c2] = lw;
        sp2(o[nt][2] * i1, o[nt][3] * i1, hw, lw);
        g_AVh[((size_t)sg1 * BATCH + b) * 512 + c2] = hw;
        g_AVl[((size_t)sg1 * BATCH + b) * 512 + c2] = lw;
    }
}

// ---------------------------------------------------------------------------
extern "C" void kernel_launch(void* const* d_in, const int* in_sizes, int n_in,
                              void* d_out, int out_size)
{
    const float* inputs = (const float*)d_in[0];
    const float* enc    = (const float*)d_in[2];
    const float* u      = (const float*)d_in[3];
    const unsigned char* mask = (const unsigned char*)d_in[5];
    const float* Wkv = (const float*)d_in[6];
    const float* bkv = (const float*)d_in[7];
    const float* Wq  = (const float*)d_in[8];
    const float* bq  = (const float*)d_in[9];
    const float* Wp  = (const float*)d_in[10];
    const float* bp  = (const float*)d_in[11];
    float* out = (float*)d_out;

    const int GSMEM = 3 * STG * 4;                         // 62976 B
    const int ASMEM = (8 * KVBUF + 2 * 128 * PADP) * 4;    // 110592 B
    cudaFuncSetAttribute(proj_gemm, cudaFuncAttributeMaxDynamicSharedMemorySize, GSMEM);
    cudaFuncSetAttribute(out_gemm,  cudaFuncAttributeMaxDynamicSharedMemorySize, GSMEM);
    cudaFuncSetAttribute(attn_bf16, cudaFuncAttributeMaxDynamicSharedMemorySize, ASMEM);

    dim3 blk(256);
    conv_w<<<2048, blk>>>(Wkv, Wq, Wp);
    conv_x<<<4096, blk>>>(enc, inputs);
    mask_scan<<<dim3(16, 32), blk>>>(mask);
    proj_gemm<<<768, blk, GSMEM>>>(bkv, bq, u);
    conv_v<<<2048, blk>>>();
    attn_bf16<<<dim3(S_LEN / 128, BATCH * HEADS), blk, ASMEM>>>(mask);
    out_gemm<<<256, blk, GSMEM>>>(bp, out);
}

// round 16
// speedup vs baseline: 1.0747x; 1.0150x over previous
#include <cuda_runtime.h>
#include <math.h>
#include <stdint.h>

#define S_LEN 2048
#define T_LEN 2048
#define BATCH 2
#define EDIM  1024
#define HEADS 16
#define HDIM  64
#define HD    (HEADS*HDIM)   /* 1024 */

// ---------------- scratch (static device globals; no allocation) ----------
__device__ uint32_t g_encH[4096*512], g_encL[4096*512];   // enc  (T*B, E/2)
__device__ uint32_t g_inH [4096*512], g_inL [4096*512];   // inp  (S*B, E/2)
__device__ uint32_t g_WkvH[512*2048], g_WkvL[512*2048];   // Wkv  (E/2, 2HD)
__device__ uint32_t g_WqH [512*1024], g_WqL [512*1024];   // Wq   (E/2, HD)
__device__ uint32_t g_WpH [512*1024], g_WpL [512*1024];   // Wp   (HD/2, E)
__device__ uint32_t g_KhT[BATCH*HEADS*32*T_LEN], g_KlT[BATCH*HEADS*32*T_LEN]; // (B,H,D/2,T)
__device__ uint32_t g_Qh[BATCH*HEADS*S_LEN*32], g_Ql[BATCH*HEADS*S_LEN*32];   // (B,H,S,D/2)
__device__ uint32_t g_Vh2[BATCH*HEADS*(T_LEN/2)*HDIM], g_Vl2[BATCH*HEADS*(T_LEN/2)*HDIM]; // (B,H,T/2,D)
__device__ uint32_t g_AVh[4096*512], g_AVl[4096*512];     // (S*B, HD/2)
__device__ int      g_mflag[16*32];                       // per (s-block, j-tile)

// ---------------- bf16 split helpers ---------------------------------------
__device__ __forceinline__ uint32_t bfbits(float x) {
    uint32_t u = __float_as_uint(x);
    return (u + 0x7FFFu + ((u >> 16) & 1u)) & 0xFFFF0000u;
}
__device__ __forceinline__ void sp2(float e, float o, uint32_t& hw, uint32_t& lw) {
    uint32_t he = bfbits(e), ho = bfbits(o);
    float re = e - __uint_as_float(he);
    float ro = o - __uint_as_float(ho);
    hw = __byte_perm(he, ho, 0x7632);
    lw = __byte_perm(bfbits(re), bfbits(ro), 0x7632);
}
__device__ __forceinline__ void mma_bf16(float* c, uint32_t a0, uint32_t a1,
                                         uint32_t a2, uint32_t a3,
                                         uint32_t b0, uint32_t b1) {
    asm volatile(
        "mma.sync.aligned.m16n8k16.row.col.f32.bf16.bf16.f32 "
        "{%0,%1,%2,%3}, {%4,%5,%6,%7}, {%8,%9}, {%0,%1,%2,%3};"
        : "+f"(c[0]), "+f"(c[1]), "+f"(c[2]), "+f"(c[3])
        : "r"(a0), "r"(a1), "r"(a2), "r"(a3), "r"(b0), "r"(b1));
}
__device__ __forceinline__ uint32_t smem_u32(const void* p) {
    uint32_t a;
    asm("{ .reg .u64 t; cvta.to.shared.u64 t, %1; cvt.u32.u64 %0, t; }"
        : "=r"(a) : "l"(p));
    return a;
}
__device__ __forceinline__ void cpa16(uint32_t dst, const uint32_t* src) {
    asm volatile("cp.async.cg.shared.global [%0], [%1], 16;"
                 :: "r"(dst), "l"(src) : "memory");
}
__device__ __forceinline__ void cpa8(uint32_t dst, const uint32_t* src) {
    asm volatile("cp.async.ca.shared.global [%0], [%1], 8;"
                 :: "r"(dst), "l"(src) : "memory");
}
#define CP_COMMIT() asm volatile("cp.async.commit_group;" ::: "memory")

// ===========================================================================
// prep kernel: weight conversions + activation conversions + mask pre-scan,
// all in ONE launch (block-range dispatch).
//   [0,1024)      Wkv convert
//   [1024,1536)   Wq convert
//   [1536,2048)   Wp convert
//   [2048,6144)   enc / inputs convert
//   [6144,6656)   mask tile-flag scan
// ===========================================================================
__device__ __forceinline__ void conv_b_body(const float* W, uint32_t* Wh,
                                            uint32_t* Wl, int N, int idx) {
    int k2 = idx / (N / 4), n4 = (idx % (N / 4)) * 4;
    const float* r0 = W + (size_t)(2 * k2) * N + n4;
    float4 a = *(const float4*)r0;
    float4 b = *(const float4*)(r0 + N);
    uint4 h, l;
    sp2(a.x, b.x, h.x, l.x); sp2(a.y, b.y, h.y, l.y);
    sp2(a.z, b.z, h.z, l.z); sp2(a.w, b.w, h.w, l.w);
    *(uint4*)(Wh + (size_t)k2 * N + n4) = h;
    *(uint4*)(Wl + (size_t)k2 * N + n4) = l;
}

__global__ __launch_bounds__(256) void prep(
    const float* __restrict__ Wkv, const float* __restrict__ Wq,
    const float* __restrict__ Wp,  const float* __restrict__ enc,
    const float* __restrict__ inp, const unsigned char* __restrict__ mask)
{
    int bx = blockIdx.x;
    if (bx < 1024) {
        conv_b_body(Wkv, g_WkvH, g_WkvL, 2048, bx * 256 + threadIdx.x);
        return;
    }
    if (bx < 1536) {
        conv_b_body(Wq, g_WqH, g_WqL, 1024, (bx - 1024) * 256 + threadIdx.x);
        return;
    }
    if (bx < 2048) {
        conv_b_body(Wp, g_WpH, g_WpL, 1024, (bx - 1536) * 256 + threadIdx.x);
        return;
    }
    if (bx < 6144) {
        int i = bx - 2048;
        const float* A = (i < 2048) ? enc : inp;
        uint32_t* Ah = (i < 2048) ? g_encH : g_inH;
        uint32_t* Al = (i < 2048) ? g_encL : g_inL;
        int idx = (i & 2047) * 256 + threadIdx.x;
        int m = idx >> 7, c8 = (idx & 127) * 8;
        float4 f0 = *(const float4*)(A + (size_t)m * 1024 + c8);
        float4 f1 = *(const float4*)(A + (size_t)m * 1024 + c8 + 4);
        uint4 h, l;
        sp2(f0.x, f0.y, h.x, l.x); sp2(f0.z, f0.w, h.y, l.y);
        sp2(f1.x, f1.y, h.z, l.z); sp2(f1.z, f1.w, h.w, l.w);
        *(uint4*)(Ah + (size_t)m * 512 + c8 / 2) = h;
        *(uint4*)(Al + (size_t)m * 512 + c8 / 2) = l;
        return;
    }
    // mask tile-flag scan: i = sblk*32 + jt
    int i = bx - 6144;
    int sblk = i >> 5, jt = i & 31;
    const unsigned char* base = mask + (size_t)(sblk * 128) * T_LEN + jt * 64;
    uint32_t m = 0;
    #pragma unroll
    for (int it = 0; it < 2; it++) {
        int idx = threadIdx.x + it * 256;
        int r = idx >> 2, c16 = (idx & 3) * 16;
        uint4 v = *(const uint4*)(base + (size_t)r * T_LEN + c16);
        m |= v.x | v.y | v.z | v.w;
    }
    int any = __syncthreads_or((int)m);
    if (threadIdx.x == 0) g_mflag[i] = any;
}

// ===========================================================================
// 3x-bf16 GEMM core: cp.async 3-stage pipeline (R12 config), 2 CTA/SM.
// MODE 0 epilogue now also writes V pre-split (t-paired) directly.
// ===========================================================================
#define PADA 12
#define PADB 136
#define A_SZ (128*PADA)          /* 1536 */
#define B_SZ (8*PADB)            /* 1088 */
#define STG  (2*A_SZ + 2*B_SZ)   /* 5248 u32 per stage */

template<int MODE>
__device__ __forceinline__ void gemm_core(
    const float* __restrict__ bias, const float* __restrict__ u,
    float* __restrict__ out, int m0, int n0, uint32_t* sm)
{
    constexpr int N = (MODE == 0) ? 2048 : 1024;
    const uint32_t* Ahg = (MODE == 0) ? g_encH : (MODE == 1) ? g_inH : g_AVh;
    const uint32_t* Alg = (MODE == 0) ? g_encL : (MODE == 1) ? g_inL : g_AVl;
    const uint32_t* Bhg = (MODE == 0) ? g_WkvH : (MODE == 1) ? g_WqH : g_WpH;
    const uint32_t* Blg = (MODE == 0) ? g_WkvL : (MODE == 1) ? g_WqL : g_WpL;

    const int tid  = threadIdx.x;
    const int wid  = tid >> 5, lane = tid & 31;
    const int g    = lane >> 2, tg = lane & 3;
    const int wm   = wid >> 2,  wn = wid & 3;

    const int aRow = tid >> 2;
    const int aKp  = (tid & 3) * 2;
    const int bKp  = tid >> 5;
    const int bCol = (tid & 31) * 4;

    const uint32_t smb = smem_u32(sm);

    #define GEMM_LOAD(st, k2) do { \
        uint32_t sb = smb + (st) * (STG * 4); \
        uint32_t aoff0 = (uint32_t)(aRow * PADA + aKp) * 4; \
        uint32_t aoff1 = (uint32_t)((aRow + 64) * PADA + aKp) * 4; \
        cpa8(sb + aoff0,                    Ahg + (size_t)(m0 + aRow)      * 512 + (k2) + aKp); \
        cpa8(sb + aoff1,                    Ahg + (size_t)(m0 + aRow + 64) * 512 + (k2) + aKp); \
        cpa8(sb + A_SZ * 4 + aoff0,         Alg + (size_t)(m0 + aRow)      * 512 + (k2) + aKp); \
        cpa8(sb + A_SZ * 4 + aoff1,         Alg + (size_t)(m0 + aRow + 64) * 512 + (k2) + aKp); \
        uint32_t boff = (uint32_t)(bKp * PADB + bCol) * 4; \
        cpa16(sb + 2 * A_SZ * 4 + boff,            Bhg + (size_t)((k2) + bKp) * N + n0 + bCol); \
        cpa16(sb + (2 * A_SZ + B_SZ) * 4 + boff,   Blg + (size_t)((k2) + bKp) * N + n0 + bCol); \
    } while (0)

    float acc[4][4][4] = {};

    GEMM_LOAD(0, 0); CP_COMMIT();
    GEMM_LOAD(1, 8); CP_COMMIT();

    const int NKB = 64;
    int st = 0;
    for (int kb = 0; kb < NKB; kb++) {
        if (kb < NKB - 1) {
            asm volatile("cp.async.wait_group 1;" ::: "memory");
        } else {
            asm volatile("cp.async.wait_group 0;" ::: "memory");
        }
        __syncthreads();
        if (kb + 2 < NKB) {
            int st2 = (st + 2 >= 3) ? st - 1 : st + 2;
            GEMM_LOAD(st2, (kb + 2) * 8);
            CP_COMMIT();
        }

        uint32_t* Ah = sm + st * STG;
        uint32_t* Al = Ah + A_SZ;
        uint32_t* Bh = Ah + 2 * A_SZ;
        uint32_t* Bl = Ah + 2 * A_SZ + B_SZ;

        uint32_t ah[4][4], al4[4][4];
        #pragma unroll
        for (int mt = 0; mt < 4; mt++) {
            int r = wm * 64 + mt * 16 + g;
            ah[mt][0]  = Ah[r * PADA + tg];
            ah[mt][1]  = Ah[(r + 8) * PADA + tg];
            ah[mt][2]  = Ah[r * PADA + tg + 4];
            ah[mt][3]  = Ah[(r + 8) * PADA + tg + 4];
            al4[mt][0] = Al[r * PADA + tg];
            al4[mt][1] = Al[(r + 8) * PADA + tg];
            al4[mt][2] = Al[r * PADA + tg + 4];
            al4[mt][3] = Al[(r + 8) * PADA + tg + 4];
        }
        uint32_t bh[4][2], bl4r[4][2];
        #pragma unroll
        for (int nt = 0; nt < 4; nt++) {
            int c = wn * 32 + nt * 8 + g;
            bh[nt][0]   = Bh[tg * PADB + c];
            bh[nt][1]   = Bh[(tg + 4) * PADB + c];
            bl4r[nt][0] = Bl[tg * PADB + c];
            bl4r[nt][1] = Bl[(tg + 4) * PADB + c];
        }
        #pragma unroll
        for (int mt = 0; mt < 4; mt++)
            #pragma unroll
            for (int nt = 0; nt < 4; nt++) {
                float* c = acc[mt][nt];
                mma_bf16(c, ah[mt][0], ah[mt][1], ah[mt][2], ah[mt][3],
                            bh[nt][0], bh[nt][1]);
                mma_bf16(c, ah[mt][0], ah[mt][1], ah[mt][2], ah[mt][3],
                            bl4r[nt][0], bl4r[nt][1]);
                mma_bf16(c, al4[mt][0], al4[mt][1], al4[mt][2], al4[mt][3],
                            bh[nt][0], bh[nt][1]);
            }

        st = (st + 1 >= 3) ? 0 : st + 1;
    }
    #undef GEMM_LOAD

    // ---------------- epilogue ------------------------------------------
    #pragma unroll
    for (int mt = 0; mt < 4; mt++) {
        #pragma unroll
        for (int nt = 0; nt < 4; nt++) {
            int n  = n0 + wn * 32 + nt * 8 + tg * 2;
            int mA = m0 + wm * 64 + mt * 16 + g;
            float bs0 = __ldg(bias + n), bs1 = __ldg(bias + n + 1);
            float v00 = acc[mt][nt][0] + bs0;
            float v01 = acc[mt][nt][1] + bs1;
            float v10 = acc[mt][nt][2] + bs0;
            float v11 = acc[mt][nt][3] + bs1;
            int t0 = mA >> 1, bb = mA & 1;
            int t1 = (mA + 8) >> 1;
            if (MODE == 0) {
                if (n < HD) {
                    int h = n >> 6, d2 = (n & 63) >> 1;
                    size_t base = ((size_t)(bb * HEADS + h)) * 32 * T_LEN + (size_t)d2 * T_LEN;
                    uint32_t hw, lw;
                    sp2(v00, v01, hw, lw);
                    g_KhT[base + t0] = hw;
                    g_KlT[base + t0] = lw;
                    sp2(v10, v11, hw, lw);
                    g_KhT[base + t1] = hw;
                    g_KlT[base + t1] = lw;
                } else {
                    // V: pack (t, t+1) pairs directly (rows g, g+2 <-> lane, lane+8)
                    int nn = n - HD;
                    int h = nn >> 6, d = nn & 63;
                    float p00 = __shfl_down_sync(0xffffffffu, v00, 8);
                    float p01 = __shfl_down_sync(0xffffffffu, v01, 8);
                    float p10 = __shfl_down_sync(0xffffffffu, v10, 8);
                    float p11 = __shfl_down_sync(0xffffffffu, v11, 8);
                    if ((g & 2) == 0) {
                        size_t base = ((size_t)(bb * HEADS + h)) * (T_LEN / 2) * HDIM;
                        int t2a = mA >> 2;          // rows mA, mA+2 -> t even pair
                        int t2b = (mA + 8) >> 2;    // rows mA+8, mA+10
                        uint32_t hw, lw;
                        sp2(v00, p00, hw, lw);
                        g_Vh2[base + (size_t)t2a * HDIM + d]     = hw;
                        g_Vl2[base + (size_t)t2a * HDIM + d]     = lw;
                        sp2(v01, p01, hw, lw);
                        g_Vh2[base + (size_t)t2a * HDIM + d + 1] = hw;
                        g_Vl2[base + (size_t)t2a * HDIM + d + 1] = lw;
                        sp2(v10, p10, hw, lw);
                        g_Vh2[base + (size_t)t2b * HDIM + d]     = hw;
                        g_Vl2[base + (size_t)t2b * HDIM + d]     = lw;
                        sp2(v11, p11, hw, lw);
                        g_Vh2[base + (size_t)t2b * HDIM + d + 1] = hw;
                        g_Vl2[base + (size_t)t2b * HDIM + d + 1] = lw;
                    }
                }
            } else if (MODE == 1) {
                float u0 = __ldg(u + n), u1 = __ldg(u + n + 1);
                int h = n >> 6, d2 = (n & 63) >> 1;
                size_t base = ((size_t)(bb * HEADS + h)) * S_LEN;
                uint32_t hw, lw;
                sp2(v00 + u0, v01 + u1, hw, lw);
                g_Qh[(base + t0) * 32 + d2] = hw;
                g_Ql[(base + t0) * 32 + d2] = lw;
                sp2(v10 + u0, v11 + u1, hw, lw);
                g_Qh[(base + t1) * 32 + d2] = hw;
                g_Ql[(base + t1) * 32 + d2] = lw;
            } else {
                out[(size_t)mA * EDIM + n]           = v00;
                out[(size_t)mA * EDIM + n + 1]       = v01;
                out[(size_t)(mA + 8) * EDIM + n]     = v10;
                out[(size_t)(mA + 8) * EDIM + n + 1] = v11;
            }
        }
    }
}

// merged kv + q projection: blocks [0,512) -> kv, [512,768) -> q
__global__ __launch_bounds__(256, 2) void proj_gemm(
    const float* __restrict__ bkv, const float* __restrict__ bq,
    const float* __restrict__ u)
{
    extern __shared__ uint32_t sm[];
    int bx = blockIdx.x;
    if (bx < 512) {
        gemm_core<0>(bkv, nullptr, nullptr, (bx >> 4) * 128, (bx & 15) * 128, sm);
    } else {
        int i = bx - 512;
        gemm_core<1>(bq, u, nullptr, (i >> 3) * 128, (i & 7) * 128, sm);
    }
}

__global__ __launch_bounds__(256, 2) void out_gemm(
    const float* __restrict__ bp, float* __restrict__ out)
{
    extern __shared__ uint32_t sm[];
    gemm_core<2>(bp, nullptr, out, (blockIdx.x >> 3) * 128, (blockIdx.x & 7) * 128, sm);
}

// ===========================================================================
// Flash attention, 3x-bf16, cp.async double-buffered K/V, ONE barrier/tile.
// ===========================================================================
#define PADT 72
#define PADP 36
#define KVBUF (32*PADT)

__global__ __launch_bounds__(256, 2) void attn_bf16(const unsigned char* __restrict__ mask)
{
    extern __shared__ uint32_t smu[];
    uint32_t* Ph = smu + 8 * KVBUF;
    uint32_t* Pl = Ph + 128 * PADP;

    const int bh = blockIdx.y;
    const int b  = bh >> 4;
    const int h  = bh & 15;
    const int s0 = blockIdx.x * 128;
    const int tid = threadIdx.x;
    const int wid = tid >> 5, lane = tid & 31;
    const int g   = lane >> 2, tg = lane & 3;
    const int rowA = wid * 16 + g;

    const uint32_t* KhTg = g_KhT + (size_t)bh * 32 * T_LEN;
    const uint32_t* KlTg = g_KlT + (size_t)bh * 32 * T_LEN;
    const uint32_t* Vh2g = g_Vh2 + (size_t)bh * (T_LEN / 2) * HDIM;
    const uint32_t* Vl2g = g_Vl2 + (size_t)bh * (T_LEN / 2) * HDIM;

    const uint32_t smb = smem_u32(smu);
    const int lr  = tid >> 4;
    const int lc4 = (tid & 15) * 4;

    uint32_t qh[4][4], ql[4][4];
    {
        const uint32_t* qh0 = g_Qh + ((size_t)bh * S_LEN + s0 + rowA) * 32;
        const uint32_t* qh1 = qh0 + 8 * 32;
        const uint32_t* ql0 = g_Ql + ((size_t)bh * S_LEN + s0 + rowA) * 32;
        const uint32_t* ql1 = ql0 + 8 * 32;
        #pragma unroll
        for (int ks = 0; ks < 4; ks++) {
            qh[ks][0] = qh0[ks * 8 + tg];
            qh[ks][1] = qh1[ks * 8 + tg];
            qh[ks][2] = qh0[ks * 8 + tg + 4];
            qh[ks][3] = qh1[ks * 8 + tg + 4];
            ql[ks][0] = ql0[ks * 8 + tg];
            ql[ks][1] = ql1[ks * 8 + tg];
            ql[ks][2] = ql0[ks * 8 + tg + 4];
            ql[ks][3] = ql1[ks * 8 + tg + 4];
        }
    }

    #define LOAD_KV(bf, j0) do { \
        uint32_t kbp = smb + (bf) * (4 * KVBUF * 4); \
        int r0_ = lr, r1_ = lr + 16; \
        uint32_t off0 = (uint32_t)(r0_ * PADT + lc4) * 4; \
        uint32_t off1 = (uint32_t)(r1_ * PADT + lc4) * 4; \
        cpa16(kbp + off0,                 KhTg + (size_t)r0_ * T_LEN + (j0) + lc4); \
        cpa16(kbp + off1,                 KhTg + (size_t)r1_ * T_LEN + (j0) + lc4); \
        cpa16(kbp + KVBUF * 4 + off0,     KlTg + (size_t)r0_ * T_LEN + (j0) + lc4); \
        cpa16(kbp + KVBUF * 4 + off1,     KlTg + (size_t)r1_ * T_LEN + (j0) + lc4); \
        cpa16(kbp + 2 * KVBUF * 4 + off0, Vh2g + (size_t)(((j0) >> 1) + r0_) * HDIM + lc4); \
        cpa16(kbp + 2 * KVBUF * 4 + off1, Vh2g + (size_t)(((j0) >> 1) + r1_) * HDIM + lc4); \
        cpa16(kbp + 3 * KVBUF * 4 + off0, Vl2g + (size_t)(((j0) >> 1) + r0_) * HDIM + lc4); \
        cpa16(kbp + 3 * KVBUF * 4 + off1, Vl2g + (size_t)(((j0) >> 1) + r1_) * HDIM + lc4); \
    } while (0)

    float o[8][4] = {};
    float m0 = -1e30f, m1 = -1e30f, l0 = 0.f, l1 = 0.f;

    LOAD_KV(0, 0);
    CP_COMMIT();

    for (int jt = 0; jt < 32; jt++) {
        const int j0 = jt << 6;
        const int buf = jt & 1;

        asm volatile("cp.async.wait_group 0;" ::: "memory");
        int any_mask = g_mflag[blockIdx.x * 32 + jt];
        __syncthreads();

        if (jt < 31) {
            LOAD_KV(buf ^ 1, j0 + 64);
            CP_COMMIT();
        }

        uint32_t* Kh = smu + buf * 4 * KVBUF;
        uint32_t* Kl = Kh + KVBUF;
        uint32_t* Vh = Kh + 2 * KVBUF;
        uint32_t* Vl = Kh + 3 * KVBUF;

        float sc[8][4] = {};
        #pragma unroll
        for (int ks = 0; ks < 4; ks++) {
            #pragma unroll
            for (int nt = 0; nt < 8; nt++) {
                int n = nt * 8 + g;
                uint32_t b0h = Kh[(ks * 8 + tg)     * PADT + n];
                uint32_t b1h = Kh[(ks * 8 + tg + 4) * PADT + n];
                uint32_t b0l = Kl[(ks * 8 + tg)     * PADT + n];
                uint32_t b1l = Kl[(ks * 8 + tg + 4) * PADT + n];
                mma_bf16(sc[nt], qh[ks][0], qh[ks][1], qh[ks][2], qh[ks][3], b0h, b1h);
                mma_bf16(sc[nt], qh[ks][0], qh[ks][1], qh[ks][2], qh[ks][3], b0l, b1l);
                mma_bf16(sc[nt], ql[ks][0], ql[ks][1], ql[ks][2], ql[ks][3], b0h, b1h);
            }
        }

        #pragma unroll
        for (int nt = 0; nt < 8; nt++) {
            sc[nt][0] *= 0.125f; sc[nt][1] *= 0.125f;
            sc[nt][2] *= 0.125f; sc[nt][3] *= 0.125f;
        }
        if (any_mask) {
            int sg0 = s0 + rowA, sg1 = sg0 + 8;
            #pragma unroll
            for (int nt = 0; nt < 8; nt++) {
                int cg = j0 + nt * 8 + tg * 2;
                const unsigned char* m0p = mask + (size_t)sg0 * T_LEN + cg;
                const unsigned char* m1p = mask + (size_t)sg1 * T_LEN + cg;
                if (m0p[0]) sc[nt][0] = -INFINITY;
                if (m0p[1]) sc[nt][1] = -INFINITY;
                if (m1p[0]) sc[nt][2] = -INFINITY;
                if (m1p[1]) sc[nt][3] = -INFINITY;
            }
        }

        float mx0 = -1e30f, mx1 = -1e30f;
        #pragma unroll
        for (int nt = 0; nt < 8; nt++) {
            mx0 = fmaxf(mx0, fmaxf(sc[nt][0], sc[nt][1]));
            mx1 = fmaxf(mx1, fmaxf(sc[nt][2], sc[nt][3]));
        }
        mx0 = fmaxf(mx0, __shfl_xor_sync(0xffffffffu, mx0, 1));
        mx0 = fmaxf(mx0, __shfl_xor_sync(0xffffffffu, mx0, 2));
        mx1 = fmaxf(mx1, __shfl_xor_sync(0xffffffffu, mx1, 1));
        mx1 = fmaxf(mx1, __shfl_xor_sync(0xffffffffu, mx1, 2));

        float mn0 = fmaxf(m0, mx0), mn1 = fmaxf(m1, mx1);
        float cr0 = __expf(m0 - mn0), cr1 = __expf(m1 - mn1);
        float ps0 = 0.f, ps1 = 0.f;
        #pragma unroll
        for (int nt = 0; nt < 8; nt++) {
            sc[nt][0] = __expf(sc[nt][0] - mn0);
            sc[nt][1] = __expf(sc[nt][1] - mn0);
            sc[nt][2] = __expf(sc[nt][2] - mn1);
            sc[nt][3] = __expf(sc[nt][3] - mn1);
            ps0 += sc[nt][0] + sc[nt][1];
            ps1 += sc[nt][2] + sc[nt][3];
        }
        ps0 += __shfl_xor_sync(0xffffffffu, ps0, 1);
        ps0 += __shfl_xor_sync(0xffffffffu, ps0, 2);
        ps1 += __shfl_xor_sync(0xffffffffu, ps1, 1);
        ps1 += __shfl_xor_sync(0xffffffffu, ps1, 2);
        l0 = l0 * cr0 + ps0; m0 = mn0;
        l1 = l1 * cr1 + ps1; m1 = mn1;
        #pragma unroll
        for (int nt = 0; nt < 8; nt++) {
            o[nt][0] *= cr0; o[nt][1] *= cr0;
            o[nt][2] *= cr1; o[nt][3] *= cr1;
        }

        #pragma unroll
        for (int nt = 0; nt < 8; nt++) {
            int c2 = nt * 4 + tg;
            uint32_t hw, lw;
            sp2(sc[nt][0], sc[nt][1], hw, lw);
            Ph[rowA * PADP + c2] = hw; Pl[rowA * PADP + c2] = lw;
            sp2(sc[nt][2], sc[nt][3], hw, lw);
            Ph[(rowA + 8) * PADP + c2] = hw; Pl[(rowA + 8) * PADP + c2] = lw;
        }
        __syncwarp();

        #pragma unroll
        for (int ks = 0; ks < 4; ks++) {
            uint32_t ah[4], al[4];
            ah[0] = Ph[ rowA      * PADP + ks * 8 + tg];
            ah[1] = Ph[(rowA + 8) * PADP + ks * 8 + tg];
            ah[2] = Ph[ rowA      * PADP + ks * 8 + tg + 4];
            ah[3] = Ph[(rowA + 8) * PADP + ks * 8 + tg + 4];
            al[0] = Pl[ rowA      * PADP + ks * 8 + tg];
            al[1] = Pl[(rowA + 8) * PADP + ks * 8 + tg];
            al[2] = Pl[ rowA      * PADP + ks * 8 + tg + 4];
            al[3] = Pl[(rowA + 8) * PADP + ks * 8 + tg + 4];
            #pragma unroll
            for (int nt = 0; nt < 8; nt++) {
                int n = nt * 8 + g;
                uint32_t b0h = Vh[(ks * 8 + tg)     * PADT + n];
                uint32_t b1h = Vh[(ks * 8 + tg + 4) * PADT + n];
                uint32_t b0l = Vl[(ks * 8 + tg)     * PADT + n];
                uint32_t b1l = Vl[(ks * 8 + tg + 4) * PADT + n];
                mma_bf16(o[nt], ah[0], ah[1], ah[2], ah[3], b0h, b1h);
                mma_bf16(o[nt], ah[0], ah[1], ah[2], ah[3], b0l, b1l);
                mma_bf16(o[nt], al[0], al[1], al[2], al[3], b0h, b1h);
            }
        }
    }

    float i0 = 1.f / l0, i1 = 1.f / l1;
    int sg0 = s0 + rowA, sg1 = sg0 + 8;
    #pragma unroll
    for (int nt = 0; nt < 8; nt++) {
        int c2 = h * 32 + nt * 4 + tg;
        uint32_t hw, lw;
        sp2(o[nt][0] * i0, o[nt][1] * i0, hw, lw);
        g_AVh[((size_t)sg0 * BATCH + b) * 512 + c2] = hw;
        g_AVl[((size_t)sg0 * BATCH + b) * 512 + c2] = lw;
        sp2(o[nt][2] * i1, o[nt][3] * i1, hw, lw);
        g_AVh[((size_t)sg1 * BATCH + b) * 512 + c2] = hw;
        g_AVl[((size_t)sg1 * BATCH + b) * 512 + c2] = lw;
    }
}

// ---------------------------------------------------------------------------
extern "C" void kernel_launch(void* const* d_in, const int* in_sizes, int n_in,
                              void* d_out, int out_size)
{
    const float* inputs = (const float*)d_in[0];
    const float* enc    = (const float*)d_in[2];
    const float* u      = (const float*)d_in[3];
    const unsigned char* mask = (const unsigned char*)d_in[5];
    const float* Wkv = (const float*)d_in[6];
    const float* bkv = (const float*)d_in[7];
    const float* Wq  = (const float*)d_in[8];
    const float* bq  = (const float*)d_in[9];
    const float* Wp  = (const float*)d_in[10];
    const float* bp  = (const float*)d_in[11];
    float* out = (float*)d_out;

    const int GSMEM = 3 * STG * 4;                         // 62976 B
    const int ASMEM = (8 * KVBUF + 2 * 128 * PADP) * 4;    // 110592 B
    cudaFuncSetAttribute(proj_gemm, cudaFuncAttributeMaxDynamicSharedMemorySize, GSMEM);
    cudaFuncSetAttribute(out_gemm,  cudaFuncAttributeMaxDynamicSharedMemorySize, GSMEM);
    cudaFuncSetAttribute(attn_bf16, cudaFuncAttributeMaxDynamicSharedMemorySize, ASMEM);

    dim3 blk(256);
    prep<<<6656, blk>>>(Wkv, Wq, Wp, enc, inputs, mask);
    proj_gemm<<<768, blk, GSMEM>>>(bkv, bq, u);
    attn_bf16<<<dim3(S_LEN / 128, BATCH * HEADS), blk, ASMEM>>>(mask);
    out_gemm<<<256, blk, GSMEM>>>(bp, out);
}

// round 17
// speedup vs baseline: 1.2803x; 1.1913x over previous
#include <cuda_runtime.h>
#include <cuda_fp16.h>
#include <math.h>
#include <stdint.h>

#define S_LEN 2048
#define T_LEN 2048
#define BATCH 2
#define EDIM  1024
#define HEADS 16
#define HDIM  64
#define HD    (HEADS*HDIM)   /* 1024 */

// ---------------- scratch (static device globals; no allocation) ----------
__device__ uint32_t g_encH[4096*512], g_encL[4096*512];   // enc  (T*B, E/2) bf16
__device__ uint32_t g_inH [4096*512], g_inL [4096*512];   // inp  (S*B, E/2) bf16
__device__ uint32_t g_WkvH[512*2048], g_WkvL[512*2048];   // Wkv  bf16
__device__ uint32_t g_WqH [512*1024], g_WqL [512*1024];   // Wq   bf16
__device__ uint32_t g_WpH [512*1024], g_WpL [512*1024];   // Wp   bf16
__device__ uint32_t g_KhT[BATCH*HEADS*32*T_LEN];          // K fp16 hi (B,H,D/2,T)
__device__ uint32_t g_Qh[BATCH*HEADS*S_LEN*32], g_Ql[BATCH*HEADS*S_LEN*32]; // Q fp16 hi/lo
__device__ uint32_t g_Vh2[BATCH*HEADS*(T_LEN/2)*HDIM];    // V fp16 hi (B,H,T/2,D)
__device__ uint32_t g_AVh[4096*512], g_AVl[4096*512];     // AV bf16 hi/lo (S*B, HD/2)
__device__ int      g_mflag[16*32];

// ---------------- bf16 split helpers ---------------------------------------
__device__ __forceinline__ uint32_t bfbits(float x) {
    uint32_t u = __float_as_uint(x);
    return (u + 0x7FFFu + ((u >> 16) & 1u)) & 0xFFFF0000u;
}
__device__ __forceinline__ void sp2(float e, float o, uint32_t& hw, uint32_t& lw) {
    uint32_t he = bfbits(e), ho = bfbits(o);
    float re = e - __uint_as_float(he);
    float ro = o - __uint_as_float(ho);
    hw = __byte_perm(he, ho, 0x7632);
    lw = __byte_perm(bfbits(re), bfbits(ro), 0x7632);
}
// ---------------- fp16 helpers ---------------------------------------------
__device__ __forceinline__ uint32_t h2pack(float e, float o) {
    __half2 h = __floats2half2_rn(e, o);
    return *(uint32_t*)&h;
}
__device__ __forceinline__ void sp2h(float e, float o, uint32_t& hw, uint32_t& lw) {
    __half2 h = __floats2half2_rn(e, o);
    float re = e - __half2float(__low2half(h));
    float ro = o - __half2float(__high2half(h));
    __half2 l = __floats2half2_rn(re, ro);
    hw = *(uint32_t*)&h;
    lw = *(uint32_t*)&l;
}
__device__ __forceinline__ void mma_bf16(float* c, uint32_t a0, uint32_t a1,
                                         uint32_t a2, uint32_t a3,
                                         uint32_t b0, uint32_t b1) {
    asm volatile(
        "mma.sync.aligned.m16n8k16.row.col.f32.bf16.bf16.f32 "
        "{%0,%1,%2,%3}, {%4,%5,%6,%7}, {%8,%9}, {%0,%1,%2,%3};"
        : "+f"(c[0]), "+f"(c[1]), "+f"(c[2]), "+f"(c[3])
        : "r"(a0), "r"(a1), "r"(a2), "r"(a3), "r"(b0), "r"(b1));
}
__device__ __forceinline__ void mma_f16(float* c, uint32_t a0, uint32_t a1,
                                        uint32_t a2, uint32_t a3,
                                        uint32_t b0, uint32_t b1) {
    asm volatile(
        "mma.sync.aligned.m16n8k16.row.col.f32.f16.f16.f32 "
        "{%0,%1,%2,%3}, {%4,%5,%6,%7}, {%8,%9}, {%0,%1,%2,%3};"
        : "+f"(c[0]), "+f"(c[1]), "+f"(c[2]), "+f"(c[3])
        : "r"(a0), "r"(a1), "r"(a2), "r"(a3), "r"(b0), "r"(b1));
}
__device__ __forceinline__ uint32_t smem_u32(const void* p) {
    uint32_t a;
    asm("{ .reg .u64 t; cvta.to.shared.u64 t, %1; cvt.u32.u64 %0, t; }"
        : "=r"(a) : "l"(p));
    return a;
}
__device__ __forceinline__ void cpa16(uint32_t dst, const uint32_t* src) {
    asm volatile("cp.async.cg.shared.global [%0], [%1], 16;"
                 :: "r"(dst), "l"(src) : "memory");
}
__device__ __forceinline__ void cpa8(uint32_t dst, const uint32_t* src) {
    asm volatile("cp.async.ca.shared.global [%0], [%1], 8;"
                 :: "r"(dst), "l"(src) : "memory");
}
#define CP_COMMIT() asm volatile("cp.async.commit_group;" ::: "memory")

// ===========================================================================
// prep kernel (unchanged: bf16 weight/activation conversions + mask scan)
// ===========================================================================
__device__ __forceinline__ void conv_b_body(const float* W, uint32_t* Wh,
                                            uint32_t* Wl, int N, int idx) {
    int k2 = idx / (N / 4), n4 = (idx % (N / 4)) * 4;
    const float* r0 = W + (size_t)(2 * k2) * N + n4;
    float4 a = *(const float4*)r0;
    float4 b = *(const float4*)(r0 + N);
    uint4 h, l;
    sp2(a.x, b.x, h.x, l.x); sp2(a.y, b.y, h.y, l.y);
    sp2(a.z, b.z, h.z, l.z); sp2(a.w, b.w, h.w, l.w);
    *(uint4*)(Wh + (size_t)k2 * N + n4) = h;
    *(uint4*)(Wl + (size_t)k2 * N + n4) = l;
}

__global__ __launch_bounds__(256) void prep(
    const float* __restrict__ Wkv, const float* __restrict__ Wq,
    const float* __restrict__ Wp,  const float* __restrict__ enc,
    const float* __restrict__ inp, const unsigned char* __restrict__ mask)
{
    int bx = blockIdx.x;
    if (bx < 1024) {
        conv_b_body(Wkv, g_WkvH, g_WkvL, 2048, bx * 256 + threadIdx.x);
        return;
    }
    if (bx < 1536) {
        conv_b_body(Wq, g_WqH, g_WqL, 1024, (bx - 1024) * 256 + threadIdx.x);
        return;
    }
    if (bx < 2048) {
        conv_b_body(Wp, g_WpH, g_WpL, 1024, (bx - 1536) * 256 + threadIdx.x);
        return;
    }
    if (bx < 6144) {
        int i = bx - 2048;
        const float* A = (i < 2048) ? enc : inp;
        uint32_t* Ah = (i < 2048) ? g_encH : g_inH;
        uint32_t* Al = (i < 2048) ? g_encL : g_inL;
        int idx = (i & 2047) * 256 + threadIdx.x;
        int m = idx >> 7, c8 = (idx & 127) * 8;
        float4 f0 = *(const float4*)(A + (size_t)m * 1024 + c8);
        float4 f1 = *(const float4*)(A + (size_t)m * 1024 + c8 + 4);
        uint4 h, l;
        sp2(f0.x, f0.y, h.x, l.x); sp2(f0.z, f0.w, h.y, l.y);
        sp2(f1.x, f1.y, h.z, l.z); sp2(f1.z, f1.w, h.w, l.w);
        *(uint4*)(Ah + (size_t)m * 512 + c8 / 2) = h;
        *(uint4*)(Al + (size_t)m * 512 + c8 / 2) = l;
        return;
    }
    int i = bx - 6144;
    int sblk = i >> 5, jt = i & 31;
    const unsigned char* base = mask + (size_t)(sblk * 128) * T_LEN + jt * 64;
    uint32_t m = 0;
    #pragma unroll
    for (int it = 0; it < 2; it++) {
        int idx = threadIdx.x + it * 256;
        int r = idx >> 2, c16 = (idx & 3) * 16;
        uint4 v = *(const uint4*)(base + (size_t)r * T_LEN + c16);
        m |= v.x | v.y | v.z | v.w;
    }
    int any = __syncthreads_or((int)m);
    if (threadIdx.x == 0) g_mflag[i] = any;
}

// ===========================================================================
// 3x-bf16 GEMM core (R12 mainloop). MODE 0/1 epilogues emit fp16 K/V/Q.
// ===========================================================================
#define PADA 12
#define PADB 136
#define A_SZ (128*PADA)
#define B_SZ (8*PADB)
#define STG  (2*A_SZ + 2*B_SZ)

template<int MODE>
__device__ __forceinline__ void gemm_core(
    const float* __restrict__ bias, const float* __restrict__ u,
    float* __restrict__ out, int m0, int n0, uint32_t* sm)
{
    constexpr int N = (MODE == 0) ? 2048 : 1024;
    const uint32_t* Ahg = (MODE == 0) ? g_encH : (MODE == 1) ? g_inH : g_AVh;
    const uint32_t* Alg = (MODE == 0) ? g_encL : (MODE == 1) ? g_inL : g_AVl;
    const uint32_t* Bhg = (MODE == 0) ? g_WkvH : (MODE == 1) ? g_WqH : g_WpH;
    const uint32_t* Blg = (MODE == 0) ? g_WkvL : (MODE == 1) ? g_WqL : g_WpL;

    const int tid  = threadIdx.x;
    const int wid  = tid >> 5, lane = tid & 31;
    const int g    = lane >> 2, tg = lane & 3;
    const int wm   = wid >> 2,  wn = wid & 3;

    const int aRow = tid >> 2;
    const int aKp  = (tid & 3) * 2;
    const int bKp  = tid >> 5;
    const int bCol = (tid & 31) * 4;

    const uint32_t smb = smem_u32(sm);

    #define GEMM_LOAD(st, k2) do { \
        uint32_t sb = smb + (st) * (STG * 4); \
        uint32_t aoff0 = (uint32_t)(aRow * PADA + aKp) * 4; \
        uint32_t aoff1 = (uint32_t)((aRow + 64) * PADA + aKp) * 4; \
        cpa8(sb + aoff0,                    Ahg + (size_t)(m0 + aRow)      * 512 + (k2) + aKp); \
        cpa8(sb + aoff1,                    Ahg + (size_t)(m0 + aRow + 64) * 512 + (k2) + aKp); \
        cpa8(sb + A_SZ * 4 + aoff0,         Alg + (size_t)(m0 + aRow)      * 512 + (k2) + aKp); \
        cpa8(sb + A_SZ * 4 + aoff1,         Alg + (size_t)(m0 + aRow + 64) * 512 + (k2) + aKp); \
        uint32_t boff = (uint32_t)(bKp * PADB + bCol) * 4; \
        cpa16(sb + 2 * A_SZ * 4 + boff,            Bhg + (size_t)((k2) + bKp) * N + n0 + bCol); \
        cpa16(sb + (2 * A_SZ + B_SZ) * 4 + boff,   Blg + (size_t)((k2) + bKp) * N + n0 + bCol); \
    } while (0)

    float acc[4][4][4] = {};

    GEMM_LOAD(0, 0); CP_COMMIT();
    GEMM_LOAD(1, 8); CP_COMMIT();

    const int NKB = 64;
    int st = 0;
    for (int kb = 0; kb < NKB; kb++) {
        if (kb < NKB - 1) {
            asm volatile("cp.async.wait_group 1;" ::: "memory");
        } else {
            asm volatile("cp.async.wait_group 0;" ::: "memory");
        }
        __syncthreads();
        if (kb + 2 < NKB) {
            int st2 = (st + 2 >= 3) ? st - 1 : st + 2;
            GEMM_LOAD(st2, (kb + 2) * 8);
            CP_COMMIT();
        }

        uint32_t* Ah = sm + st * STG;
        uint32_t* Al = Ah + A_SZ;
        uint32_t* Bh = Ah + 2 * A_SZ;
        uint32_t* Bl = Ah + 2 * A_SZ + B_SZ;

        uint32_t ah[4][4], al4[4][4];
        #pragma unroll
        for (int mt = 0; mt < 4; mt++) {
            int r = wm * 64 + mt * 16 + g;
            ah[mt][0]  = Ah[r * PADA + tg];
            ah[mt][1]  = Ah[(r + 8) * PADA + tg];
            ah[mt][2]  = Ah[r * PADA + tg + 4];
            ah[mt][3]  = Ah[(r + 8) * PADA + tg + 4];
            al4[mt][0] = Al[r * PADA + tg];
            al4[mt][1] = Al[(r + 8) * PADA + tg];
            al4[mt][2] = Al[r * PADA + tg + 4];
            al4[mt][3] = Al[(r + 8) * PADA + tg + 4];
        }
        uint32_t bh[4][2], bl4r[4][2];
        #pragma unroll
        for (int nt = 0; nt < 4; nt++) {
            int c = wn * 32 + nt * 8 + g;
            bh[nt][0]   = Bh[tg * PADB + c];
            bh[nt][1]   = Bh[(tg + 4) * PADB + c];
            bl4r[nt][0] = Bl[tg * PADB + c];
            bl4r[nt][1] = Bl[(tg + 4) * PADB + c];
        }
        #pragma unroll
        for (int mt = 0; mt < 4; mt++)
            #pragma unroll
            for (int nt = 0; nt < 4; nt++) {
                float* c = acc[mt][nt];
                mma_bf16(c, ah[mt][0], ah[mt][1], ah[mt][2], ah[mt][3],
                            bh[nt][0], bh[nt][1]);
                mma_bf16(c, ah[mt][0], ah[mt][1], ah[mt][2], ah[mt][3],
                            bl4r[nt][0], bl4r[nt][1]);
                mma_bf16(c, al4[mt][0], al4[mt][1], al4[mt][2], al4[mt][3],
                            bh[nt][0], bh[nt][1]);
            }

        st = (st + 1 >= 3) ? 0 : st + 1;
    }
    #undef GEMM_LOAD

    // ---------------- epilogue ------------------------------------------
    #pragma unroll
    for (int mt = 0; mt < 4; mt++) {
        #pragma unroll
        for (int nt = 0; nt < 4; nt++) {
            int n  = n0 + wn * 32 + nt * 8 + tg * 2;
            int mA = m0 + wm * 64 + mt * 16 + g;
            float bs0 = __ldg(bias + n), bs1 = __ldg(bias + n + 1);
            float v00 = acc[mt][nt][0] + bs0;
            float v01 = acc[mt][nt][1] + bs1;
            float v10 = acc[mt][nt][2] + bs0;
            float v11 = acc[mt][nt][3] + bs1;
            int t0 = mA >> 1, bb = mA & 1;
            int t1 = (mA + 8) >> 1;
            if (MODE == 0) {
                if (n < HD) {
                    int h = n >> 6, d2 = (n & 63) >> 1;
                    size_t base = ((size_t)(bb * HEADS + h)) * 32 * T_LEN + (size_t)d2 * T_LEN;
                    g_KhT[base + t0] = h2pack(v00, v01);
                    g_KhT[base + t1] = h2pack(v10, v11);
                } else {
                    int nn = n - HD;
                    int h = nn >> 6, d = nn & 63;
                    float p00 = __shfl_down_sync(0xffffffffu, v00, 8);
                    float p01 = __shfl_down_sync(0xffffffffu, v01, 8);
                    float p10 = __shfl_down_sync(0xffffffffu, v10, 8);
                    float p11 = __shfl_down_sync(0xffffffffu, v11, 8);
                    if ((g & 2) == 0) {
                        size_t base = ((size_t)(bb * HEADS + h)) * (T_LEN / 2) * HDIM;
                        int t2a = mA >> 2;
                        int t2b = (mA + 8) >> 2;
                        g_Vh2[base + (size_t)t2a * HDIM + d]     = h2pack(v00, p00);
                        g_Vh2[base + (size_t)t2a * HDIM + d + 1] = h2pack(v01, p01);
                        g_Vh2[base + (size_t)t2b * HDIM + d]     = h2pack(v10, p10);
                        g_Vh2[base + (size_t)t2b * HDIM + d + 1] = h2pack(v11, p11);
                    }
                }
            } else if (MODE == 1) {
                float u0 = __ldg(u + n), u1 = __ldg(u + n + 1);
                int h = n >> 6, d2 = (n & 63) >> 1;
                size_t base = ((size_t)(bb * HEADS + h)) * S_LEN;
                uint32_t hw, lw;
                sp2h(v00 + u0, v01 + u1, hw, lw);
                g_Qh[(base + t0) * 32 + d2] = hw;
                g_Ql[(base + t0) * 32 + d2] = lw;
                sp2h(v10 + u0, v11 + u1, hw, lw);
                g_Qh[(base + t1) * 32 + d2] = hw;
                g_Ql[(base + t1) * 32 + d2] = lw;
            } else {
                out[(size_t)mA * EDIM + n]           = v00;
                out[(size_t)mA * EDIM + n + 1]       = v01;
                out[(size_t)(mA + 8) * EDIM + n]     = v10;
                out[(size_t)(mA + 8) * EDIM + n + 1] = v11;
            }
        }
    }
}

__global__ __launch_bounds__(256, 2) void proj_gemm(
    const float* __restrict__ bkv, const float* __restrict__ bq,
    const float* __restrict__ u)
{
    extern __shared__ uint32_t sm[];
    int bx = blockIdx.x;
    if (bx < 512) {
        gemm_core<0>(bkv, nullptr, nullptr, (bx >> 4) * 128, (bx & 15) * 128, sm);
    } else {
        int i = bx - 512;
        gemm_core<1>(bq, u, nullptr, (i >> 3) * 128, (i & 7) * 128, sm);
    }
}

__global__ __launch_bounds__(256, 2) void out_gemm(
    const float* __restrict__ bp, float* __restrict__ out)
{
    extern __shared__ uint32_t sm[];
    gemm_core<2>(bp, nullptr, out, (blockIdx.x >> 3) * 128, (blockIdx.x & 7) * 128, sm);
}

// ===========================================================================
// Flash attention, 2-term fp16 (hi.hi + lo.hi), K/V hi-only, cp.async
// double-buffered, one barrier/tile. smem = 73728 B.
// ===========================================================================
#define PADT 72
#define PADP 36
#define KVBUF (32*PADT)

__global__ __launch_bounds__(256, 2) void attn_f16(const unsigned char* __restrict__ mask)
{
    extern __shared__ uint32_t smu[];
    uint32_t* Ph = smu + 4 * KVBUF;
    uint32_t* Pl = Ph + 128 * PADP;

    const int bh = blockIdx.y;
    const int b  = bh >> 4;
    const int h  = bh & 15;
    const int s0 = blockIdx.x * 128;
    const int tid = threadIdx.x;
    const int wid = tid >> 5, lane = tid & 31;
    const int g   = lane >> 2, tg = lane & 3;
    const int rowA = wid * 16 + g;

    const uint32_t* KhTg = g_KhT + (size_t)bh * 32 * T_LEN;
    const uint32_t* Vh2g = g_Vh2 + (size_t)bh * (T_LEN / 2) * HDIM;

    const uint32_t smb = smem_u32(smu);
    const int lr  = tid >> 4;
    const int lc4 = (tid & 15) * 4;

    uint32_t qh[4][4], ql[4][4];
    {
        const uint32_t* qh0 = g_Qh + ((size_t)bh * S_LEN + s0 + rowA) * 32;
        const uint32_t* qh1 = qh0 + 8 * 32;
        const uint32_t* ql0 = g_Ql + ((size_t)bh * S_LEN + s0 + rowA) * 32;
        const uint32_t* ql1 = ql0 + 8 * 32;
        #pragma unroll
        for (int ks = 0; ks < 4; ks++) {
            qh[ks][0] = qh0[ks * 8 + tg];
            qh[ks][1] = qh1[ks * 8 + tg];
            qh[ks][2] = qh0[ks * 8 + tg + 4];
            qh[ks][3] = qh1[ks * 8 + tg + 4];
            ql[ks][0] = ql0[ks * 8 + tg];
            ql[ks][1] = ql1[ks * 8 + tg];
            ql[ks][2] = ql0[ks * 8 + tg + 4];
            ql[ks][3] = ql1[ks * 8 + tg + 4];
        }
    }

    #define LOAD_KV(bf, j0) do { \
        uint32_t kbp = smb + (bf) * (2 * KVBUF * 4); \
        int r0_ = lr, r1_ = lr + 16; \
        uint32_t off0 = (uint32_t)(r0_ * PADT + lc4) * 4; \
        uint32_t off1 = (uint32_t)(r1_ * PADT + lc4) * 4; \
        cpa16(kbp + off0,             KhTg + (size_t)r0_ * T_LEN + (j0) + lc4); \
        cpa16(kbp + off1,             KhTg + (size_t)r1_ * T_LEN + (j0) + lc4); \
        cpa16(kbp + KVBUF * 4 + off0, Vh2g + (size_t)(((j0) >> 1) + r0_) * HDIM + lc4); \
        cpa16(kbp + KVBUF * 4 + off1, Vh2g + (size_t)(((j0) >> 1) + r1_) * HDIM + lc4); \
    } while (0)

    float o[8][4] = {};
    float m0 = -1e30f, m1 = -1e30f, l0 = 0.f, l1 = 0.f;

    LOAD_KV(0, 0);
    CP_COMMIT();

    for (int jt = 0; jt < 32; jt++) {
        const int j0 = jt << 6;
        const int buf = jt & 1;

        asm volatile("cp.async.wait_group 0;" ::: "memory");
        int any_mask = g_mflag[blockIdx.x * 32 + jt];
        __syncthreads();

        if (jt < 31) {
            LOAD_KV(buf ^ 1, j0 + 64);
            CP_COMMIT();
        }

        uint32_t* Kh = smu + buf * 2 * KVBUF;
        uint32_t* Vh = Kh + KVBUF;

        float sc[8][4] = {};
        #pragma unroll
        for (int ks = 0; ks < 4; ks++) {
            #pragma unroll
            for (int nt = 0; nt < 8; nt++) {
                int n = nt * 8 + g;
                uint32_t b0h = Kh[(ks * 8 + tg)     * PADT + n];
                uint32_t b1h = Kh[(ks * 8 + tg + 4) * PADT + n];
                mma_f16(sc[nt], qh[ks][0], qh[ks][1], qh[ks][2], qh[ks][3], b0h, b1h);
                mma_f16(sc[nt], ql[ks][0], ql[ks][1], ql[ks][2], ql[ks][3], b0h, b1h);
            }
        }

        #pragma unroll
        for (int nt = 0; nt < 8; nt++) {
            sc[nt][0] *= 0.125f; sc[nt][1] *= 0.125f;
            sc[nt][2] *= 0.125f; sc[nt][3] *= 0.125f;
        }
        if (any_mask) {
            int sg0 = s0 + rowA, sg1 = sg0 + 8;
            #pragma unroll
            for (int nt = 0; nt < 8; nt++) {
                int cg = j0 + nt * 8 + tg * 2;
                const unsigned char* m0p = mask + (size_t)sg0 * T_LEN + cg;
                const unsigned char* m1p = mask + (size_t)sg1 * T_LEN + cg;
                if (m0p[0]) sc[nt][0] = -INFINITY;
                if (m0p[1]) sc[nt][1] = -INFINITY;
                if (m1p[0]) sc[nt][2] = -INFINITY;
                if (m1p[1]) sc[nt][3] = -INFINITY;
            }
        }

        float mx0 = -1e30f, mx1 = -1e30f;
        #pragma unroll
        for (int nt = 0; nt < 8; nt++) {
            mx0 = fmaxf(mx0, fmaxf(sc[nt][0], sc[nt][1]));
            mx1 = fmaxf(mx1, fmaxf(sc[nt][2], sc[nt][3]));
        }
        mx0 = fmaxf(mx0, __shfl_xor_sync(0xffffffffu, mx0, 1));
        mx0 = fmaxf(mx0, __shfl_xor_sync(0xffffffffu, mx0, 2));
        mx1 = fmaxf(mx1, __shfl_xor_sync(0xffffffffu, mx1, 1));
        mx1 = fmaxf(mx1, __shfl_xor_sync(0xffffffffu, mx1, 2));

        float mn0 = fmaxf(m0, mx0), mn1 = fmaxf(m1, mx1);
        float cr0 = __expf(m0 - mn0), cr1 = __expf(m1 - mn1);
        float ps0 = 0.f, ps1 = 0.f;
        #pragma unroll
        for (int nt = 0; nt < 8; nt++) {
            sc[nt][0] = __expf(sc[nt][0] - mn0);
            sc[nt][1] = __expf(sc[nt][1] - mn0);
            sc[nt][2] = __expf(sc[nt][2] - mn1);
            sc[nt][3] = __expf(sc[nt][3] - mn1);
            ps0 += sc[nt][0] + sc[nt][1];
            ps1 += sc[nt][2] + sc[nt][3];
        }
        ps0 += __shfl_xor_sync(0xffffffffu, ps0, 1);
        ps0 += __shfl_xor_sync(0xffffffffu, ps0, 2);
        ps1 += __shfl_xor_sync(0xffffffffu, ps1, 1);
        ps1 += __shfl_xor_sync(0xffffffffu, ps1, 2);
        l0 = l0 * cr0 + ps0; m0 = mn0;
        l1 = l1 * cr1 + ps1; m1 = mn1;
        #pragma unroll
        for (int nt = 0; nt < 8; nt++) {
            o[nt][0] *= cr0; o[nt][1] *= cr0;
            o[nt][2] *= cr1; o[nt][3] *= cr1;
        }

        #pragma unroll
        for (int nt = 0; nt < 8; nt++) {
            int c2 = nt * 4 + tg;
            uint32_t hw, lw;
            sp2h(sc[nt][0], sc[nt][1], hw, lw);
            Ph[rowA * PADP + c2] = hw; Pl[rowA * PADP + c2] = lw;
            sp2h(sc[nt][2], sc[nt][3], hw, lw);
            Ph[(rowA + 8) * PADP + c2] = hw; Pl[(rowA + 8) * PADP + c2] = lw;
        }
        __syncwarp();

        #pragma unroll
        for (int ks = 0; ks < 4; ks++) {
            uint32_t ah[4], al[4];
            ah[0] = Ph[ rowA      * PADP + ks * 8 + tg];
            ah[1] = Ph[(rowA + 8) * PADP + ks * 8 + tg];
            ah[2] = Ph[ rowA      * PADP + ks * 8 + tg + 4];
            ah[3] = Ph[(rowA + 8) * PADP + ks * 8 + tg + 4];
            al[0] = Pl[ rowA      * PADP + ks * 8 + tg];
            al[1] = Pl[(rowA + 8) * PADP + ks * 8 + tg];
            al[2] = Pl[ rowA      * PADP + ks * 8 + tg + 4];
            al[3] = Pl[(rowA + 8) * PADP + ks * 8 + tg + 4];
            #pragma unroll
            for (int nt = 0; nt < 8; nt++) {
                int n = nt * 8 + g;
                uint32_t b0h = Vh[(ks * 8 + tg)     * PADT + n];
                uint32_t b1h = Vh[(ks * 8 + tg + 4) * PADT + n];
                mma_f16(o[nt], ah[0], ah[1], ah[2], ah[3], b0h, b1h);
                mma_f16(o[nt], al[0], al[1], al[2], al[3], b0h, b1h);
            }
        }
    }

    float i0 = 1.f / l0, i1 = 1.f / l1;
    int sg0 = s0 + rowA, sg1 = sg0 + 8;
    #pragma unroll
    for (int nt = 0; nt < 8; nt++) {
        int c2 = h * 32 + nt * 4 + tg;
        uint32_t hw, lw;
        sp2(o[nt][0] * i0, o[nt][1] * i0, hw, lw);
        g_AVh[((size_t)sg0 * BATCH + b) * 512 + c2] = hw;
        g_AVl[((size_t)sg0 * BATCH + b) * 512 + c2] = lw;
        sp2(o[nt][2] * i1, o[nt][3] * i1, hw, lw);
        g_AVh[((size_t)sg1 * BATCH + b) * 512 + c2] = hw;
        g_AVl[((size_t)sg1 * BATCH + b) * 512 + c2] = lw;
    }
}

// ---------------------------------------------------------------------------
extern "C" void kernel_launch(void* const* d_in, const int* in_sizes, int n_in,
                              void* d_out, int out_size)
{
    const float* inputs = (const float*)d_in[0];
    const float* enc    = (const float*)d_in[2];
    const float* u      = (const float*)d_in[3];
    const unsigned char* mask = (const unsigned char*)d_in[5];
    const float* Wkv = (const float*)d_in[6];
    const float* bkv = (const float*)d_in[7];
    const float* Wq  = (const float*)d_in[8];
    const float* bq  = (const float*)d_in[9];
    const float* Wp  = (const float*)d_in[10];
    const float* bp  = (const float*)d_in[11];
    float* out = (float*)d_out;

    const int GSMEM = 3 * STG * 4;                         // 62976 B
    const int ASMEM = (4 * KVBUF + 2 * 128 * PADP) * 4;    // 73728 B
    cudaFuncSetAttribute(proj_gemm, cudaFuncAttributeMaxDynamicSharedMemorySize, GSMEM);
    cudaFuncSetAttribute(out_gemm,  cudaFuncAttributeMaxDynamicSharedMemorySize, GSMEM);
    cudaFuncSetAttribute(attn_f16,  cudaFuncAttributeMaxDynamicSharedMemorySize, ASMEM);

    dim3 blk(256);
    prep<<<6656, blk>>>(Wkv, Wq, Wp, enc, inputs, mask);
    proj_gemm<<<768, blk, GSMEM>>>(bkv, bq, u);
    attn_f16<<<dim3(S_LEN / 128, BATCH * HEADS), blk, ASMEM>>>(mask);
    out_gemm<<<256, blk, GSMEM>>>(bp, out);
}